// round 4
// baseline (speedup 1.0000x reference)
#include <cuda_runtime.h>
#include <math.h>

// Problem constants (fixed by the reference): B=4096, OUT=1024, IN=1024
#define BATCH 4096
#define OUTF  1024
#define INF   1024
#define BN_EPS 1e-5f

// ---------------------------------------------------------------------------
// Scratch (no allocations allowed -> __device__ globals)
// ---------------------------------------------------------------------------
__device__ float g_psum[8][OUTF];     // partial sums per batch-slice
__device__ float g_psqsum[8][OUTF];   // partial sum of squares per batch-slice
__device__ float g_scale[OUTF];       // rstd * gamma
__device__ float g_shift[OUTF];       // beta - mean * rstd * gamma

// ---------------------------------------------------------------------------
// Kernel 1: fused polynomial GEMM
//   Y[b,o] = sum_i x[b,i]*c1[o,i] + x^2*c2[o,i] + x^3*c3[o,i]
// (bias rowsum omitted: it is constant per column o and cancels exactly
//  under the batch-mean subtraction in BatchNorm.)
// Tiling: BM=128, BN=128, BK=8; 256 threads; 8x8 microtile per thread.
// ---------------------------------------------------------------------------
#define BM 128
#define BNT 128
#define BK 8
#define TM 8
#define TN 8

__global__ __launch_bounds__(256, 1)
void poly_gemm_kernel(const float* __restrict__ X,
                      const float* __restrict__ C1,
                      const float* __restrict__ C2,
                      const float* __restrict__ C3,
                      float* __restrict__ Y)
{
    __shared__ float As [BK][BM];
    __shared__ float B1s[BK][BNT];
    __shared__ float B2s[BK][BNT];
    __shared__ float B3s[BK][BNT];

    const int block_b = blockIdx.y * BM;   // batch-row base
    const int block_o = blockIdx.x * BNT;  // out-col base
    const int tid = threadIdx.x;

    // microtile coordinates: 16 x 16 thread grid, each thread 8x8
    const int tr = tid >> 4;   // 0..15  -> rows tr*8 .. tr*8+7
    const int tc = tid & 15;   // 0..15  -> cols tc*8 .. tc*8+7

    // global-load assignment: 256 threads, 128 rows x 8 k -> one float4 each
    const int ld_row  = tid >> 1;         // 0..127
    const int ld_col4 = (tid & 1) * 4;    // 0 or 4

    const float* xp  = X  + (size_t)(block_b + ld_row) * INF + ld_col4;
    const float* c1p = C1 + (size_t)(block_o + ld_row) * INF + ld_col4;
    const float* c2p = C2 + (size_t)(block_o + ld_row) * INF + ld_col4;
    const float* c3p = C3 + (size_t)(block_o + ld_row) * INF + ld_col4;

    float acc[TM][TN];
    #pragma unroll
    for (int i = 0; i < TM; i++)
        #pragma unroll
        for (int j = 0; j < TN; j++)
            acc[i][j] = 0.0f;

    for (int k0 = 0; k0 < INF; k0 += BK) {
        // stage global loads in registers before the barrier
        const float4 av  = *reinterpret_cast<const float4*>(xp  + k0);
        const float4 b1v = *reinterpret_cast<const float4*>(c1p + k0);
        const float4 b2v = *reinterpret_cast<const float4*>(c2p + k0);
        const float4 b3v = *reinterpret_cast<const float4*>(c3p + k0);

        __syncthreads();   // previous tile's compute done before overwrite

        As[ld_col4 + 0][ld_row] = av.x;
        As[ld_col4 + 1][ld_row] = av.y;
        As[ld_col4 + 2][ld_row] = av.z;
        As[ld_col4 + 3][ld_row] = av.w;

        B1s[ld_col4 + 0][ld_row] = b1v.x;
        B1s[ld_col4 + 1][ld_row] = b1v.y;
        B1s[ld_col4 + 2][ld_row] = b1v.z;
        B1s[ld_col4 + 3][ld_row] = b1v.w;

        B2s[ld_col4 + 0][ld_row] = b2v.x;
        B2s[ld_col4 + 1][ld_row] = b2v.y;
        B2s[ld_col4 + 2][ld_row] = b2v.z;
        B2s[ld_col4 + 3][ld_row] = b2v.w;

        B3s[ld_col4 + 0][ld_row] = b3v.x;
        B3s[ld_col4 + 1][ld_row] = b3v.y;
        B3s[ld_col4 + 2][ld_row] = b3v.z;
        B3s[ld_col4 + 3][ld_row] = b3v.w;

        __syncthreads();

        #pragma unroll
        for (int kk = 0; kk < BK; kk++) {
            float a[TM], b1[TN], b2[TN], b3[TN];
            const float* ap  = &As [kk][tr * TM];
            const float* b1p = &B1s[kk][tc * TN];
            const float* b2p = &B2s[kk][tc * TN];
            const float* b3p = &B3s[kk][tc * TN];
            #pragma unroll
            for (int i = 0; i < TM; i++) a[i]  = ap[i];
            #pragma unroll
            for (int j = 0; j < TN; j++) { b1[j] = b1p[j]; b2[j] = b2p[j]; b3[j] = b3p[j]; }

            #pragma unroll
            for (int i = 0; i < TM; i++) {
                const float a1 = a[i];
                const float a2 = a1 * a1;
                const float a3 = a2 * a1;
                #pragma unroll
                for (int j = 0; j < TN; j++) {
                    acc[i][j] = fmaf(a1, b1[j], acc[i][j]);
                    acc[i][j] = fmaf(a2, b2[j], acc[i][j]);
                    acc[i][j] = fmaf(a3, b3[j], acc[i][j]);
                }
            }
        }
    }

    // epilogue: vectorized store of the 8x8 microtile
    #pragma unroll
    for (int i = 0; i < TM; i++) {
        float* yrow = Y + (size_t)(block_b + tr * TM + i) * OUTF + block_o + tc * TN;
        float4 v0 = make_float4(acc[i][0], acc[i][1], acc[i][2], acc[i][3]);
        float4 v1 = make_float4(acc[i][4], acc[i][5], acc[i][6], acc[i][7]);
        reinterpret_cast<float4*>(yrow)[0] = v0;
        reinterpret_cast<float4*>(yrow)[1] = v1;
    }
}

// ---------------------------------------------------------------------------
// Kernel 2: BN partial statistics. grid (OUTF/32, 8); block 256 = 8 rows x 32 cols.
// Each block covers 32 output columns over a 512-row batch slice.
// Deterministic (no float atomics).
// ---------------------------------------------------------------------------
__global__ __launch_bounds__(256)
void bn_partial_kernel(const float* __restrict__ Y)
{
    const int c = threadIdx.x & 31;
    const int r = threadIdx.x >> 5;            // 0..7
    const int o = blockIdx.x * 32 + c;
    const int b_base = blockIdx.y * 512;

    float s = 0.0f, ss = 0.0f;
    #pragma unroll 8
    for (int b = b_base + r; b < b_base + 512; b += 8) {
        const float v = Y[(size_t)b * OUTF + o];
        s += v;
        ss = fmaf(v, v, ss);
    }

    __shared__ float sh_s[8][32];
    __shared__ float sh_ss[8][32];
    sh_s[r][c] = s;
    sh_ss[r][c] = ss;
    __syncthreads();

    if (r == 0) {
        float S = 0.0f, SS = 0.0f;
        #pragma unroll
        for (int i = 0; i < 8; i++) { S += sh_s[i][c]; SS += sh_ss[i][c]; }
        g_psum[blockIdx.y][o]   = S;
        g_psqsum[blockIdx.y][o] = SS;
    }
}

// ---------------------------------------------------------------------------
// Kernel 3: finalize stats -> per-column affine (scale, shift)
// ---------------------------------------------------------------------------
__global__ __launch_bounds__(256)
void bn_finalize_kernel(const float* __restrict__ gamma,
                        const float* __restrict__ beta)
{
    const int o = blockIdx.x * 256 + threadIdx.x;
    float S = 0.0f, SS = 0.0f;
    #pragma unroll
    for (int i = 0; i < 8; i++) { S += g_psum[i][o]; SS += g_psqsum[i][o]; }
    const float inv_n = 1.0f / (float)BATCH;
    const float mean = S * inv_n;
    const float var  = SS * inv_n - mean * mean;
    const float rstd = rsqrtf(var + BN_EPS);
    const float sc = rstd * gamma[o];
    g_scale[o] = sc;
    g_shift[o] = fmaf(-mean, sc, beta[o]);
}

// ---------------------------------------------------------------------------
// Kernel 4: apply BN in place (float4 vectorized). 1024 cols = 256 float4/row.
// ---------------------------------------------------------------------------
__global__ __launch_bounds__(256)
void bn_apply_kernel(float* __restrict__ Y)
{
    const int idx = blockIdx.x * blockDim.x + threadIdx.x;   // 0 .. (B*OUT/4)-1
    float4 v = reinterpret_cast<float4*>(Y)[idx];
    const int col = (idx & 255) * 4;
    v.x = fmaf(v.x, g_scale[col + 0], g_shift[col + 0]);
    v.y = fmaf(v.y, g_scale[col + 1], g_shift[col + 1]);
    v.z = fmaf(v.z, g_scale[col + 2], g_shift[col + 2]);
    v.w = fmaf(v.w, g_scale[col + 3], g_shift[col + 3]);
    reinterpret_cast<float4*>(Y)[idx] = v;
}

// ---------------------------------------------------------------------------
// Launcher. Inputs (metadata order): x, c1, c2, c3, bias, gamma, beta.
// bias is skipped: its per-column rowsum cancels under BN mean subtraction.
// ---------------------------------------------------------------------------
extern "C" void kernel_launch(void* const* d_in, const int* in_sizes, int n_in,
                              void* d_out, int out_size)
{
    (void)in_sizes; (void)n_in; (void)out_size;
    const float* x     = (const float*)d_in[0];
    const float* c1    = (const float*)d_in[1];
    const float* c2    = (const float*)d_in[2];
    const float* c3    = (const float*)d_in[3];
    /* d_in[4] = bias (cancels under BN) */
    const float* gamma = (const float*)d_in[5];
    const float* beta  = (const float*)d_in[6];
    float* y = (float*)d_out;

    // 1) fused polynomial GEMM -> y (pre-BN)
    {
        dim3 grid(OUTF / BNT, BATCH / BM);   // (8, 32)
        poly_gemm_kernel<<<grid, 256>>>(x, c1, c2, c3, y);
    }
    // 2) BN partial stats (deterministic two-phase)
    {
        dim3 grid(OUTF / 32, 8);             // (32, 8)
        bn_partial_kernel<<<grid, 256>>>(y);
    }
    // 3) finalize per-column scale/shift
    {
        bn_finalize_kernel<<<OUTF / 256, 256>>>(gamma, beta);
    }
    // 4) apply BN in place
    {
        const int total_f4 = (BATCH * OUTF) / 4;   // 1,048,576
        bn_apply_kernel<<<total_f4 / 256, 256>>>(y);
    }
}

// round 6
// speedup vs baseline: 2.8194x; 2.8194x over previous
#include <cuda_runtime.h>
#include <cstdint>
#include <math.h>

// Problem constants: B=4096, OUT=1024, IN=1024
#define BATCH 4096
#define OUTF  1024
#define INF   1024
#define BN_EPS 1e-5f

// ---------------------------------------------------------------------------
// Scratch (__device__ globals; no allocations allowed)
// ---------------------------------------------------------------------------
__device__ float g_psum[8][OUTF];
__device__ float g_psqsum[8][OUTF];
__device__ float g_scale[OUTF];
__device__ float g_shift[OUTF];

// ---------------------------------------------------------------------------
// Baseline-PTX helpers (sm_80+ features only; the harness compiles through
// compute_103 non-'a', so NO tcgen05 / arch-specific PTX is available).
// ---------------------------------------------------------------------------
__device__ __forceinline__ uint32_t smem_u32(const void* p) {
    uint32_t a;
    asm("{ .reg .u64 t; cvta.to.shared.u64 t, %1; cvt.u32.u64 %0, t; }" : "=r"(a) : "l"(p));
    return a;
}

__device__ __forceinline__ void cp16(uint32_t dst, const void* src) {
    asm volatile("cp.async.cg.shared.global [%0], [%1], 16;" :: "r"(dst), "l"(src));
}

__device__ __forceinline__ uint32_t f2tf32(float f) {
    uint32_t u;
    asm("cvt.rna.tf32.f32 %0, %1;" : "=r"(u) : "f"(f));
    return u;
}

// m16n8k8 tf32 tensor-core MMA (sm_80 baseline PTX; HMMA on Blackwell)
#define MMA_TF32(d, a, b) \
    asm volatile("mma.sync.aligned.m16n8k8.row.col.f32.tf32.tf32.f32 " \
        "{%0,%1,%2,%3}, {%4,%5,%6,%7}, {%8,%9}, {%0,%1,%2,%3};" \
        : "+f"((d)[0]), "+f"((d)[1]), "+f"((d)[2]), "+f"((d)[3]) \
        : "r"((a)[0]), "r"((a)[1]), "r"((a)[2]), "r"((a)[3]), \
          "r"((b)[0]), "r"((b)[1]))

// ---------------------------------------------------------------------------
// Fused polynomial GEMM (tf32 tensor cores):
//   Y[b,o] = sum_i x*c1 + x^2*c2 + x^3*c3
// (bias rowsum is constant per column o and cancels exactly under the
//  BatchNorm batch-mean subtraction -> skipped.)
//
// CTA tile 128(M) x 128(N), K chunks of 8, 256 threads = 8 warps (2m x 4n),
// warp tile 64x32 -> 4x4 m16n8k8 tiles x 3 matrices = 48 MMAs/warp/chunk.
// x^2, x^3 are derived elementwise from the x A-fragment in registers
// (full fp32 precision, then cvt to tf32) -> only ONE A tile in smem.
// cp.async double-buffered; padded smem rows (8 -> 12 floats) give
// conflict-free fragment loads.
// ---------------------------------------------------------------------------
#define TILE_M 128
#define TILE_N 128
#define KCH    8
#define NCHUNK (INF / KCH)        // 128
#define ROWF   12                 // floats per smem row (8 data + 4 pad)
#define MATF   (128 * ROWF)       // 1536 floats per matrix tile
#define STAGEF (4 * MATF)         // A + B1 + B2 + B3 = 6144 floats
#define SMEMF  (2 * STAGEF)       // double buffer = 12288 floats = 48 KB

__global__ __launch_bounds__(256, 1)
void poly_mma_kernel(const float* __restrict__ X,
                     const float* __restrict__ C1,
                     const float* __restrict__ C2,
                     const float* __restrict__ C3,
                     float* __restrict__ Y)
{
    __shared__ float sm[SMEMF];

    const int tid  = threadIdx.x;
    const int wid  = tid >> 5;
    const int lane = tid & 31;
    const int g    = lane >> 2;      // group id 0..7
    const int tig  = lane & 3;       // thread-in-group 0..3
    const int warp_m = wid >> 2;     // 0..1 -> m base = warp_m*64
    const int warp_n = wid & 3;      // 0..3 -> n base = warp_n*32

    const int block_o = blockIdx.x * TILE_N;
    const int block_b = blockIdx.y * TILE_M;

    // ---- cp.async geometry: 128 rows x 2 16B-chunks per matrix = 256 copies;
    //      each thread does 1 per matrix (4 total per chunk).
    const int lrow = tid >> 1;       // 0..127
    const int lq   = tid & 1;        // 0..1 (which 16B chunk of the 32B row)

    const float* srcA  = X  + (size_t)(block_b + lrow) * INF + lq * 4;
    const float* srcB1 = C1 + (size_t)(block_o + lrow) * INF + lq * 4;
    const float* srcB2 = C2 + (size_t)(block_o + lrow) * INF + lq * 4;
    const float* srcB3 = C3 + (size_t)(block_o + lrow) * INF + lq * 4;

    const uint32_t smbase = smem_u32(sm);
    const uint32_t dst_off = (uint32_t)(lrow * (ROWF * 4) + lq * 16);

    // accumulators: 4 m-tiles x 4 n-tiles x 4 regs
    float acc[4][4][4];
    #pragma unroll
    for (int mt = 0; mt < 4; mt++)
        #pragma unroll
        for (int nt = 0; nt < 4; nt++)
            #pragma unroll
            for (int r = 0; r < 4; r++)
                acc[mt][nt][r] = 0.0f;

    // ---- prologue: stage chunks 0 and 1
    #pragma unroll
    for (int s = 0; s < 2; s++) {
        const uint32_t base = smbase + (uint32_t)(s * STAGEF * 4) + dst_off;
        const int k0 = s * KCH;
        cp16(base,                srcA  + k0);
        cp16(base + MATF * 4,     srcB1 + k0);
        cp16(base + 2 * MATF * 4, srcB2 + k0);
        cp16(base + 3 * MATF * 4, srcB3 + k0);
        asm volatile("cp.async.commit_group;" ::: "memory");
    }

    for (int s = 0; s < NCHUNK; ++s) {
        asm volatile("cp.async.wait_group 1;" ::: "memory");
        __syncthreads();

        const float* stage = sm + (s & 1) * STAGEF;
        const float* A  = stage;
        const float* B1 = stage + MATF;
        const float* B2 = stage + 2 * MATF;
        const float* B3 = stage + 3 * MATF;

        // ---- A fragments: load x, derive x^2, x^3 in fp32, convert to tf32
        uint32_t a1[4][4], a2[4][4], a3[4][4];
        #pragma unroll
        for (int mt = 0; mt < 4; mt++) {
            const int r0 = warp_m * 64 + mt * 16 + g;
            float v[4];
            v[0] = A[r0 * ROWF + tig];
            v[1] = A[(r0 + 8) * ROWF + tig];
            v[2] = A[r0 * ROWF + tig + 4];
            v[3] = A[(r0 + 8) * ROWF + tig + 4];
            #pragma unroll
            for (int r = 0; r < 4; r++) {
                const float sq = v[r] * v[r];
                const float cu = sq * v[r];
                a1[mt][r] = f2tf32(v[r]);
                a2[mt][r] = f2tf32(sq);
                a3[mt][r] = f2tf32(cu);
            }
        }

        // ---- B fragments (3 matrices x 4 n-tiles x 2 regs)
        uint32_t b1[4][2], b2[4][2], b3[4][2];
        #pragma unroll
        for (int nt = 0; nt < 4; nt++) {
            const int n0 = warp_n * 32 + nt * 8 + g;
            b1[nt][0] = f2tf32(B1[n0 * ROWF + tig]);
            b1[nt][1] = f2tf32(B1[n0 * ROWF + tig + 4]);
            b2[nt][0] = f2tf32(B2[n0 * ROWF + tig]);
            b2[nt][1] = f2tf32(B2[n0 * ROWF + tig + 4]);
            b3[nt][0] = f2tf32(B3[n0 * ROWF + tig]);
            b3[nt][1] = f2tf32(B3[n0 * ROWF + tig + 4]);
        }

        // ---- 48 tensor-core MMAs
        #pragma unroll
        for (int mt = 0; mt < 4; mt++)
            #pragma unroll
            for (int nt = 0; nt < 4; nt++) {
                MMA_TF32(acc[mt][nt], a1[mt], b1[nt]);
                MMA_TF32(acc[mt][nt], a2[mt], b2[nt]);
                MMA_TF32(acc[mt][nt], a3[mt], b3[nt]);
            }

        __syncthreads();   // all warps done reading this buffer

        // ---- prefetch chunk s+2 into the buffer just freed
        if (s + 2 < NCHUNK) {
            const uint32_t base = smbase + (uint32_t)((s & 1) * STAGEF * 4) + dst_off;
            const int k0 = (s + 2) * KCH;
            cp16(base,                srcA  + k0);
            cp16(base + MATF * 4,     srcB1 + k0);
            cp16(base + 2 * MATF * 4, srcB2 + k0);
            cp16(base + 3 * MATF * 4, srcB3 + k0);
        }
        asm volatile("cp.async.commit_group;" ::: "memory");
    }

    // ---- epilogue: D fragment (row g / g+8, col 2*tig / 2*tig+1) -> float2
    #pragma unroll
    for (int mt = 0; mt < 4; mt++) {
        #pragma unroll
        for (int nt = 0; nt < 4; nt++) {
            const int row = block_b + warp_m * 64 + mt * 16 + g;
            const int col = block_o + warp_n * 32 + nt * 8 + 2 * tig;
            float2 lo = make_float2(acc[mt][nt][0], acc[mt][nt][1]);
            float2 hi = make_float2(acc[mt][nt][2], acc[mt][nt][3]);
            *reinterpret_cast<float2*>(Y + (size_t)row * OUTF + col) = lo;
            *reinterpret_cast<float2*>(Y + (size_t)(row + 8) * OUTF + col) = hi;
        }
    }
}

// ---------------------------------------------------------------------------
// BatchNorm kernels (unchanged from R3 — proven correct, deterministic)
// ---------------------------------------------------------------------------
__global__ __launch_bounds__(256)
void bn_partial_kernel(const float* __restrict__ Y)
{
    const int c = threadIdx.x & 31;
    const int r = threadIdx.x >> 5;
    const int o = blockIdx.x * 32 + c;
    const int b_base = blockIdx.y * 512;

    float s = 0.0f, ss = 0.0f;
    #pragma unroll 8
    for (int b = b_base + r; b < b_base + 512; b += 8) {
        const float v = Y[(size_t)b * OUTF + o];
        s += v;
        ss = fmaf(v, v, ss);
    }
    __shared__ float sh_s[8][32];
    __shared__ float sh_ss[8][32];
    sh_s[r][c] = s; sh_ss[r][c] = ss;
    __syncthreads();
    if (r == 0) {
        float S = 0.0f, SS = 0.0f;
        #pragma unroll
        for (int i = 0; i < 8; i++) { S += sh_s[i][c]; SS += sh_ss[i][c]; }
        g_psum[blockIdx.y][o] = S;
        g_psqsum[blockIdx.y][o] = SS;
    }
}

__global__ __launch_bounds__(256)
void bn_finalize_kernel(const float* __restrict__ gamma,
                        const float* __restrict__ beta)
{
    const int o = blockIdx.x * 256 + threadIdx.x;
    float S = 0.0f, SS = 0.0f;
    #pragma unroll
    for (int i = 0; i < 8; i++) { S += g_psum[i][o]; SS += g_psqsum[i][o]; }
    const float inv_n = 1.0f / (float)BATCH;
    const float mean = S * inv_n;
    const float var  = SS * inv_n - mean * mean;
    const float rstd = rsqrtf(var + BN_EPS);
    const float sc = rstd * gamma[o];
    g_scale[o] = sc;
    g_shift[o] = fmaf(-mean, sc, beta[o]);
}

__global__ __launch_bounds__(256)
void bn_apply_kernel(float* __restrict__ Y)
{
    const int idx = blockIdx.x * blockDim.x + threadIdx.x;
    float4 v = reinterpret_cast<float4*>(Y)[idx];
    const int col = (idx & 255) * 4;
    v.x = fmaf(v.x, g_scale[col + 0], g_shift[col + 0]);
    v.y = fmaf(v.y, g_scale[col + 1], g_shift[col + 1]);
    v.z = fmaf(v.z, g_scale[col + 2], g_shift[col + 2]);
    v.w = fmaf(v.w, g_scale[col + 3], g_shift[col + 3]);
    reinterpret_cast<float4*>(Y)[idx] = v;
}

// ---------------------------------------------------------------------------
// Launcher. Inputs: x, c1, c2, c3, bias(skipped: cancels under BN), gamma, beta
// ---------------------------------------------------------------------------
extern "C" void kernel_launch(void* const* d_in, const int* in_sizes, int n_in,
                              void* d_out, int out_size)
{
    (void)in_sizes; (void)n_in; (void)out_size;
    const float* x     = (const float*)d_in[0];
    const float* c1    = (const float*)d_in[1];
    const float* c2    = (const float*)d_in[2];
    const float* c3    = (const float*)d_in[3];
    const float* gamma = (const float*)d_in[5];
    const float* beta  = (const float*)d_in[6];
    float* y = (float*)d_out;

    {
        dim3 grid(OUTF / TILE_N, BATCH / TILE_M);   // (8, 32) = 256 CTAs
        poly_mma_kernel<<<grid, 256>>>(x, c1, c2, c3, y);
    }
    {
        dim3 grid(OUTF / 32, 8);
        bn_partial_kernel<<<grid, 256>>>(y);
    }
    bn_finalize_kernel<<<OUTF / 256, 256>>>(gamma, beta);
    {
        const int total_f4 = (BATCH * OUTF) / 4;
        bn_apply_kernel<<<total_f4 / 256, 256>>>(y);
    }
}

// round 7
// speedup vs baseline: 3.8979x; 1.3825x over previous
#include <cuda_runtime.h>
#include <cuda_fp16.h>
#include <cstdint>
#include <math.h>

// Problem constants: B=4096, OUT=1024, IN=1024
#define BATCH 4096
#define OUTF  1024
#define INF   1024
#define BN_EPS 1e-5f

// ---------------------------------------------------------------------------
// Scratch (__device__ globals; no allocations allowed)
// ---------------------------------------------------------------------------
__device__ float g_psum[32][OUTF];    // per-(row-block, column) partial sums
__device__ float g_psqsum[32][OUTF];
__device__ float g_scale[OUTF];
__device__ float g_shift[OUTF];

// ---------------------------------------------------------------------------
// Baseline-PTX helpers (sm_80+ only: harness compiles via compute_103 non-'a',
// so no tcgen05/arch-specific PTX is available).
// ---------------------------------------------------------------------------
__device__ __forceinline__ uint32_t smem_u32(const void* p) {
    uint32_t a;
    asm("{ .reg .u64 t; cvta.to.shared.u64 t, %1; cvt.u32.u64 %0, t; }" : "=r"(a) : "l"(p));
    return a;
}

__device__ __forceinline__ void cp16(uint32_t dst, const void* src) {
    asm volatile("cp.async.cg.shared.global [%0], [%1], 16;" :: "r"(dst), "l"(src));
}

__device__ __forceinline__ uint32_t pack_h2(float lo, float hi) {
    __half2 h = __floats2half2_rn(lo, hi);
    return *reinterpret_cast<uint32_t*>(&h);
}

// m16n8k16 fp16 tensor-core MMA (sm_80 baseline PTX), fp32 accumulate
#define MMA_F16(d, a, b) \
    asm volatile("mma.sync.aligned.m16n8k16.row.col.f32.f16.f16.f32 " \
        "{%0,%1,%2,%3}, {%4,%5,%6,%7}, {%8,%9}, {%0,%1,%2,%3};" \
        : "+f"((d)[0]), "+f"((d)[1]), "+f"((d)[2]), "+f"((d)[3]) \
        : "r"((a)[0]), "r"((a)[1]), "r"((a)[2]), "r"((a)[3]), \
          "r"((b)[0]), "r"((b)[1]))

// ---------------------------------------------------------------------------
// Fused polynomial GEMM (fp16 tensor cores, fp32 accum) + BN partial stats:
//   Y[b,o] = sum_i x*c1 + x^2*c2 + x^3*c3
// (bias rowsum is constant per column and cancels under the BN batch-mean.)
//
// CTA tile 128(M) x 128(N), K chunks of 16, 256 threads = 8 warps (2m x 4n),
// warp tile 64x32 -> 4x4 m16n8k16 tiles x 3 matrices = 48 MMAs/warp/chunk.
// x^2, x^3 derived in fp32 from the staged fp32 x, then cvt to fp16 ->
// only one A tile in smem, full-precision squaring.
// Epilogue computes per-column sum/sumsq for this 128-row block and writes
// g_psum/g_psqsum[blockIdx.y][*] -> no separate bn_partial pass.
// ---------------------------------------------------------------------------
#define TILE_M 128
#define TILE_N 128
#define KCH    16
#define NCHUNK (INF / KCH)          // 64
#define ROWF   20                   // floats per smem row (16 data + 4 pad)
#define MATF   (128 * ROWF)         // 2560 floats per matrix tile
#define STAGEF (4 * MATF)           // A + B1 + B2 + B3 = 10240 floats
#define SMEMF  (2 * STAGEF)         // double buffer = 20480 floats = 80 KB
#define SMEM_BYTES (SMEMF * 4)

__global__ __launch_bounds__(256, 1)
void poly_mma_kernel(const float* __restrict__ X,
                     const float* __restrict__ C1,
                     const float* __restrict__ C2,
                     const float* __restrict__ C3,
                     float* __restrict__ Y)
{
    extern __shared__ float sm[];

    const int tid  = threadIdx.x;
    const int wid  = tid >> 5;
    const int lane = tid & 31;
    const int g    = lane >> 2;      // 0..7
    const int tig  = lane & 3;       // 0..3
    const int warp_m = wid >> 2;     // 0..1
    const int warp_n = wid & 3;      // 0..3

    const int block_o = blockIdx.x * TILE_N;
    const int block_b = blockIdx.y * TILE_M;

    // cp.async geometry: per matrix per chunk, 128 rows x 4 16B-pieces = 512
    // copies; 256 threads -> 2 rows each (row, row+64), same q.
    const int r0c = tid >> 2;        // 0..63
    const int qc  = tid & 3;         // 0..3

    const float* srcA  = X  + (size_t)(block_b) * INF + qc * 4;
    const float* srcB1 = C1 + (size_t)(block_o) * INF + qc * 4;
    const float* srcB2 = C2 + (size_t)(block_o) * INF + qc * 4;
    const float* srcB3 = C3 + (size_t)(block_o) * INF + qc * 4;

    const uint32_t smbase = smem_u32(sm);

    float acc[4][4][4];
    #pragma unroll
    for (int mt = 0; mt < 4; mt++)
        #pragma unroll
        for (int nt = 0; nt < 4; nt++)
            #pragma unroll
            for (int r = 0; r < 4; r++)
                acc[mt][nt][r] = 0.0f;

    // ---- stage one chunk: 4 matrices x 2 rows per thread
    auto stage_chunk = [&](int s) {
        const uint32_t base = smbase + (uint32_t)((s & 1) * STAGEF * 4);
        const int k0 = s * KCH;
        #pragma unroll
        for (int i = 0; i < 2; i++) {
            const int row = r0c + 64 * i;
            const uint32_t doff = (uint32_t)(row * (ROWF * 4) + qc * 16);
            const size_t goff = (size_t)row * INF + k0;
            cp16(base + doff,                srcA  + goff);
            cp16(base + MATF * 4 + doff,     srcB1 + goff);
            cp16(base + 2 * MATF * 4 + doff, srcB2 + goff);
            cp16(base + 3 * MATF * 4 + doff, srcB3 + goff);
        }
        asm volatile("cp.async.commit_group;" ::: "memory");
    };

    stage_chunk(0);
    stage_chunk(1);

    for (int s = 0; s < NCHUNK; ++s) {
        asm volatile("cp.async.wait_group 1;" ::: "memory");
        __syncthreads();

        const float* stage = sm + (s & 1) * STAGEF;
        const float* A  = stage;
        const float* B1 = stage + MATF;
        const float* B2 = stage + 2 * MATF;
        const float* B3 = stage + 3 * MATF;

        // ---- A fragments: x (fp32) -> x, x^2, x^3 -> fp16 pairs
        uint32_t a1[4][4], a2[4][4], a3[4][4];
        #pragma unroll
        for (int mt = 0; mt < 4; mt++) {
            const int rlo = warp_m * 64 + mt * 16 + g;
            const int rhi = rlo + 8;
            float2 v[4];
            v[0] = *reinterpret_cast<const float2*>(A + rlo * ROWF + 2 * tig);      // a0
            v[1] = *reinterpret_cast<const float2*>(A + rhi * ROWF + 2 * tig);      // a1
            v[2] = *reinterpret_cast<const float2*>(A + rlo * ROWF + 2 * tig + 8);  // a2
            v[3] = *reinterpret_cast<const float2*>(A + rhi * ROWF + 2 * tig + 8);  // a3
            #pragma unroll
            for (int r = 0; r < 4; r++) {
                const float sx = v[r].x * v[r].x, sy = v[r].y * v[r].y;
                const float cx = sx * v[r].x,    cy = sy * v[r].y;
                a1[mt][r] = pack_h2(v[r].x, v[r].y);
                a2[mt][r] = pack_h2(sx, sy);
                a3[mt][r] = pack_h2(cx, cy);
            }
        }

        // ---- B fragments (col-major k16 x n8): b0 = k{2tig,2tig+1}, b1 = +8
        uint32_t b1f[4][2], b2f[4][2], b3f[4][2];
        #pragma unroll
        for (int nt = 0; nt < 4; nt++) {
            const int n0 = warp_n * 32 + nt * 8 + g;
            float2 w;
            w = *reinterpret_cast<const float2*>(B1 + n0 * ROWF + 2 * tig);
            b1f[nt][0] = pack_h2(w.x, w.y);
            w = *reinterpret_cast<const float2*>(B1 + n0 * ROWF + 2 * tig + 8);
            b1f[nt][1] = pack_h2(w.x, w.y);
            w = *reinterpret_cast<const float2*>(B2 + n0 * ROWF + 2 * tig);
            b2f[nt][0] = pack_h2(w.x, w.y);
            w = *reinterpret_cast<const float2*>(B2 + n0 * ROWF + 2 * tig + 8);
            b2f[nt][1] = pack_h2(w.x, w.y);
            w = *reinterpret_cast<const float2*>(B3 + n0 * ROWF + 2 * tig);
            b3f[nt][0] = pack_h2(w.x, w.y);
            w = *reinterpret_cast<const float2*>(B3 + n0 * ROWF + 2 * tig + 8);
            b3f[nt][1] = pack_h2(w.x, w.y);
        }

        // ---- 48 tensor-core MMAs
        #pragma unroll
        for (int mt = 0; mt < 4; mt++)
            #pragma unroll
            for (int nt = 0; nt < 4; nt++) {
                MMA_F16(acc[mt][nt], a1[mt], b1f[nt]);
                MMA_F16(acc[mt][nt], a2[mt], b2f[nt]);
                MMA_F16(acc[mt][nt], a3[mt], b3f[nt]);
            }

        __syncthreads();

        if (s + 2 < NCHUNK) stage_chunk(s + 2);
        else asm volatile("cp.async.commit_group;" ::: "memory");
    }

    // ---- epilogue 1: store Y
    #pragma unroll
    for (int mt = 0; mt < 4; mt++) {
        #pragma unroll
        for (int nt = 0; nt < 4; nt++) {
            const int row = block_b + warp_m * 64 + mt * 16 + g;
            const int col = block_o + warp_n * 32 + nt * 8 + 2 * tig;
            float2 lo = make_float2(acc[mt][nt][0], acc[mt][nt][1]);
            float2 hi = make_float2(acc[mt][nt][2], acc[mt][nt][3]);
            *reinterpret_cast<float2*>(Y + (size_t)row * OUTF + col) = lo;
            *reinterpret_cast<float2*>(Y + (size_t)(row + 8) * OUTF + col) = hi;
        }
    }

    // ---- epilogue 2: BN partial stats for this 128-row block.
    // Per thread: 8 columns (nt x c), each with 8 row-values (4 mt x 2 rows).
    float csum[4][2], csq[4][2];
    #pragma unroll
    for (int nt = 0; nt < 4; nt++)
        #pragma unroll
        for (int c = 0; c < 2; c++) {
            float s0 = 0.0f, q0 = 0.0f;
            #pragma unroll
            for (int mt = 0; mt < 4; mt++) {
                const float vlo = acc[mt][nt][c];       // row g
                const float vhi = acc[mt][nt][c + 2];   // row g+8
                s0 += vlo + vhi;
                q0 = fmaf(vlo, vlo, q0);
                q0 = fmaf(vhi, vhi, q0);
            }
            csum[nt][c] = s0;
            csq[nt][c] = q0;
        }
    // reduce over g (lanes differ in bits 2..4; tig preserved)
    #pragma unroll
    for (int d = 4; d <= 16; d <<= 1) {
        #pragma unroll
        for (int nt = 0; nt < 4; nt++)
            #pragma unroll
            for (int c = 0; c < 2; c++) {
                csum[nt][c] += __shfl_xor_sync(0xFFFFFFFFu, csum[nt][c], d);
                csq[nt][c]  += __shfl_xor_sync(0xFFFFFFFFu, csq[nt][c], d);
            }
    }
    // cross-warp (warp_m 0/1 share columns) via smem; reuse stage buffer
    float* red_sum = sm;          // [2][128]
    float* red_sq  = sm + 256;    // [2][128]
    if (g == 0) {
        #pragma unroll
        for (int nt = 0; nt < 4; nt++)
            #pragma unroll
            for (int c = 0; c < 2; c++) {
                const int col = warp_n * 32 + nt * 8 + 2 * tig + c;
                red_sum[warp_m * 128 + col] = csum[nt][c];
                red_sq [warp_m * 128 + col] = csq[nt][c];
            }
    }
    __syncthreads();
    if (tid < 128) {
        const int col = tid;
        g_psum[blockIdx.y][block_o + col]   = red_sum[col] + red_sum[128 + col];
        g_psqsum[blockIdx.y][block_o + col] = red_sq[col]  + red_sq[128 + col];
    }
}

// ---------------------------------------------------------------------------
// BN finalize: reduce 32 row-block partials -> per-column affine
// ---------------------------------------------------------------------------
__global__ __launch_bounds__(256)
void bn_finalize_kernel(const float* __restrict__ gamma,
                        const float* __restrict__ beta)
{
    const int o = blockIdx.x * 256 + threadIdx.x;
    float S = 0.0f, SS = 0.0f;
    #pragma unroll
    for (int i = 0; i < 32; i++) { S += g_psum[i][o]; SS += g_psqsum[i][o]; }
    const float inv_n = 1.0f / (float)BATCH;
    const float mean = S * inv_n;
    const float var  = SS * inv_n - mean * mean;
    const float rstd = rsqrtf(var + BN_EPS);
    const float sc = rstd * gamma[o];
    g_scale[o] = sc;
    g_shift[o] = fmaf(-mean, sc, beta[o]);
}

// ---------------------------------------------------------------------------
// BN apply in place (float4 vectorized)
// ---------------------------------------------------------------------------
__global__ __launch_bounds__(256)
void bn_apply_kernel(float* __restrict__ Y)
{
    const int idx = blockIdx.x * blockDim.x + threadIdx.x;
    float4 v = reinterpret_cast<float4*>(Y)[idx];
    const int col = (idx & 255) * 4;
    v.x = fmaf(v.x, g_scale[col + 0], g_shift[col + 0]);
    v.y = fmaf(v.y, g_scale[col + 1], g_shift[col + 1]);
    v.z = fmaf(v.z, g_scale[col + 2], g_shift[col + 2]);
    v.w = fmaf(v.w, g_scale[col + 3], g_shift[col + 3]);
    reinterpret_cast<float4*>(Y)[idx] = v;
}

// ---------------------------------------------------------------------------
// Launcher. Inputs: x, c1, c2, c3, bias(skipped: cancels under BN), gamma, beta
// ---------------------------------------------------------------------------
extern "C" void kernel_launch(void* const* d_in, const int* in_sizes, int n_in,
                              void* d_out, int out_size)
{
    (void)in_sizes; (void)n_in; (void)out_size;
    const float* x     = (const float*)d_in[0];
    const float* c1    = (const float*)d_in[1];
    const float* c2    = (const float*)d_in[2];
    const float* c3    = (const float*)d_in[3];
    const float* gamma = (const float*)d_in[5];
    const float* beta  = (const float*)d_in[6];
    float* y = (float*)d_out;

    // 80 KB dynamic smem (idempotent host-side attribute; no allocation)
    cudaFuncSetAttribute(poly_mma_kernel,
                         cudaFuncAttributeMaxDynamicSharedMemorySize, SMEM_BYTES);

    {
        dim3 grid(OUTF / TILE_N, BATCH / TILE_M);   // (8, 32) = 256 CTAs
        poly_mma_kernel<<<grid, 256, SMEM_BYTES>>>(x, c1, c2, c3, y);
    }
    bn_finalize_kernel<<<OUTF / 256, 256>>>(gamma, beta);
    {
        const int total_f4 = (BATCH * OUTF) / 4;
        bn_apply_kernel<<<total_f4 / 256, 256>>>(y);
    }
}

// round 8
// speedup vs baseline: 4.9746x; 1.2762x over previous
#include <cuda_runtime.h>
#include <cuda_fp16.h>
#include <cstdint>
#include <math.h>

// Problem constants: B=4096, OUT=1024, IN=1024
#define BATCH 4096
#define OUTF  1024
#define INF   1024
#define KTOT  3072            // 3 * INF (x | x^2 | x^3 concatenated on K)
#define BN_EPS 1e-5f

// ---------------------------------------------------------------------------
// Scratch (__device__ globals; no allocations allowed)
// ---------------------------------------------------------------------------
__device__ __half g_A[(size_t)BATCH * KTOT];   // 24 MB: [x | x^2 | x^3] fp16
__device__ __half g_B[(size_t)OUTF * KTOT];    //  6 MB: [c1 | c2 | c3] fp16
__device__ float g_psum[32][OUTF];
__device__ float g_psqsum[32][OUTF];
__device__ float g_scale[OUTF];
__device__ float g_shift[OUTF];

// ---------------------------------------------------------------------------
// Baseline-PTX helpers (sm_80+ only: harness compiles via compute_103 non-'a')
// ---------------------------------------------------------------------------
__device__ __forceinline__ uint32_t smem_u32(const void* p) {
    uint32_t a;
    asm("{ .reg .u64 t; cvta.to.shared.u64 t, %1; cvt.u32.u64 %0, t; }" : "=r"(a) : "l"(p));
    return a;
}
__device__ __forceinline__ void cp16(uint32_t dst, const void* src) {
    asm volatile("cp.async.cg.shared.global [%0], [%1], 16;" :: "r"(dst), "l"(src));
}
__device__ __forceinline__ uint32_t pack_h2(float lo, float hi) {
    __half2 h = __floats2half2_rn(lo, hi);
    return *reinterpret_cast<uint32_t*>(&h);
}

// m16n8k16 fp16 tensor-core MMA (sm_80 baseline PTX), fp32 accumulate
#define MMA_F16(d, a, b) \
    asm volatile("mma.sync.aligned.m16n8k16.row.col.f32.f16.f16.f32 " \
        "{%0,%1,%2,%3}, {%4,%5,%6,%7}, {%8,%9}, {%0,%1,%2,%3};" \
        : "+f"((d)[0]), "+f"((d)[1]), "+f"((d)[2]), "+f"((d)[3]) \
        : "r"((a)[0]), "r"((a)[1]), "r"((a)[2]), "r"((a)[3]), \
          "r"((b)[0]), "r"((b)[1]))

// ---------------------------------------------------------------------------
// Pre-pass 1: pack A = [x | x^2 | x^3] fp16.  x^2,x^3 in fp32 then cvt.
// ---------------------------------------------------------------------------
__global__ __launch_bounds__(256)
void pack_x_kernel(const float* __restrict__ X)
{
    const int idx = blockIdx.x * 256 + threadIdx.x;       // 0 .. B*IN/4-1
    const int b  = idx >> 8;
    const int k4 = (idx & 255) * 4;
    const float4 v = *reinterpret_cast<const float4*>(X + (size_t)b * INF + k4);
    float4 s, c;
    s.x = v.x * v.x; s.y = v.y * v.y; s.z = v.z * v.z; s.w = v.w * v.w;
    c.x = s.x * v.x; c.y = s.y * v.y; c.z = s.z * v.z; c.w = s.w * v.w;
    __half* rowp = g_A + (size_t)b * KTOT;
    uint2 h;
    h.x = pack_h2(v.x, v.y); h.y = pack_h2(v.z, v.w);
    *reinterpret_cast<uint2*>(rowp + k4) = h;
    h.x = pack_h2(s.x, s.y); h.y = pack_h2(s.z, s.w);
    *reinterpret_cast<uint2*>(rowp + INF + k4) = h;
    h.x = pack_h2(c.x, c.y); h.y = pack_h2(c.z, c.w);
    *reinterpret_cast<uint2*>(rowp + 2 * INF + k4) = h;
}

// ---------------------------------------------------------------------------
// Pre-pass 2: pack B = [c1 | c2 | c3] fp16.
// ---------------------------------------------------------------------------
__global__ __launch_bounds__(256)
void pack_c_kernel(const float* __restrict__ C1,
                   const float* __restrict__ C2,
                   const float* __restrict__ C3)
{
    const int idx = blockIdx.x * 256 + threadIdx.x;       // 0 .. OUT*IN/4-1
    const int o  = idx >> 8;
    const int k4 = (idx & 255) * 4;
    const size_t src = (size_t)o * INF + k4;
    __half* rowp = g_B + (size_t)o * KTOT;
    float4 v; uint2 h;
    v = *reinterpret_cast<const float4*>(C1 + src);
    h.x = pack_h2(v.x, v.y); h.y = pack_h2(v.z, v.w);
    *reinterpret_cast<uint2*>(rowp + k4) = h;
    v = *reinterpret_cast<const float4*>(C2 + src);
    h.x = pack_h2(v.x, v.y); h.y = pack_h2(v.z, v.w);
    *reinterpret_cast<uint2*>(rowp + INF + k4) = h;
    v = *reinterpret_cast<const float4*>(C3 + src);
    h.x = pack_h2(v.x, v.y); h.y = pack_h2(v.z, v.w);
    *reinterpret_cast<uint2*>(rowp + 2 * INF + k4) = h;
}

// ---------------------------------------------------------------------------
// Standard fp16 GEMM  Y = A_packed @ B_packed^T  (M=4096,N=1024,K=3072)
// + fused BN partial stats in the epilogue.
// CTA 128x128, 256 threads = 8 warps (2m x 4n), warp tile 64x32.
// K chunks of 32 (2 k16 slabs), 4-stage cp.async pipeline, 80 KB smem.
// 2 CTAs/SM -> 256 CTAs in a single wave.
// ---------------------------------------------------------------------------
#define TILE_M 128
#define TILE_N 128
#define KCH    32
#define NCHUNK (KTOT / KCH)        // 96
#define NSTAGE 4
#define RBB    80                  // bytes per smem row (64 data + 16 pad)
#define MATB   (128 * RBB)         // 10240 B per matrix tile
#define STAGEB (2 * MATB)          // 20480 B (A + B)
#define SMEM_BYTES (NSTAGE * STAGEB)   // 81920 B

__global__ __launch_bounds__(256, 2)
void poly_mma_kernel(float* __restrict__ Y)
{
    extern __shared__ char sm[];
    const uint32_t smbase = smem_u32(sm);

    const int tid  = threadIdx.x;
    const int wid  = tid >> 5;
    const int lane = tid & 31;
    const int g    = lane >> 2;      // 0..7
    const int tig  = lane & 3;       // 0..3
    const int warp_m = wid >> 2;     // 0..1
    const int warp_n = wid & 3;      // 0..3

    const int block_o = blockIdx.x * TILE_N;
    const int block_b = blockIdx.y * TILE_M;

    // cp.async geometry: 128 rows x 64 B per matrix; thread -> row tid>>1,
    // 32-byte piece (tid&1): two cp16 each for A and B.
    const int crow = tid >> 1;
    const int choff = (tid & 1) * 16;                 // half offset in row
    const __half* srcA = g_A + (size_t)(block_b + crow) * KTOT + choff;
    const __half* srcB = g_B + (size_t)(block_o + crow) * KTOT + choff;
    const uint32_t cdst = (uint32_t)(crow * RBB + (tid & 1) * 32);

    float acc[4][4][4];
    #pragma unroll
    for (int mt = 0; mt < 4; mt++)
        #pragma unroll
        for (int nt = 0; nt < 4; nt++)
            #pragma unroll
            for (int r = 0; r < 4; r++)
                acc[mt][nt][r] = 0.0f;

    auto stage_chunk = [&](int s) {
        if (s < NCHUNK) {
            const uint32_t base = smbase + (uint32_t)((s & 3) * STAGEB) + cdst;
            const int k0 = s * KCH;
            cp16(base,            srcA + k0);
            cp16(base + 16,       srcA + k0 + 8);
            cp16(base + MATB,     srcB + k0);
            cp16(base + MATB + 16, srcB + k0 + 8);
        }
        asm volatile("cp.async.commit_group;" ::: "memory");
    };

    stage_chunk(0);
    stage_chunk(1);
    stage_chunk(2);

    for (int s = 0; s < NCHUNK; ++s) {
        asm volatile("cp.async.wait_group 2;" ::: "memory");
        __syncthreads();

        stage_chunk(s + 3);   // into buffer (s+3)&3 == (s-1)&3, safe after sync

        const char* stA = sm + (s & 3) * STAGEB;
        const char* stB = stA + MATB;

        #pragma unroll
        for (int kk = 0; kk < 2; kk++) {
            const int kb = kk * 32;   // byte offset of this k16 slab

            uint32_t a[4][4];
            #pragma unroll
            for (int mt = 0; mt < 4; mt++) {
                const int rlo = warp_m * 64 + mt * 16 + g;
                const int rhi = rlo + 8;
                a[mt][0] = *reinterpret_cast<const uint32_t*>(stA + rlo * RBB + kb + tig * 4);
                a[mt][1] = *reinterpret_cast<const uint32_t*>(stA + rhi * RBB + kb + tig * 4);
                a[mt][2] = *reinterpret_cast<const uint32_t*>(stA + rlo * RBB + kb + 16 + tig * 4);
                a[mt][3] = *reinterpret_cast<const uint32_t*>(stA + rhi * RBB + kb + 16 + tig * 4);
            }
            uint32_t b[4][2];
            #pragma unroll
            for (int nt = 0; nt < 4; nt++) {
                const int n0 = warp_n * 32 + nt * 8 + g;
                b[nt][0] = *reinterpret_cast<const uint32_t*>(stB + n0 * RBB + kb + tig * 4);
                b[nt][1] = *reinterpret_cast<const uint32_t*>(stB + n0 * RBB + kb + 16 + tig * 4);
            }
            #pragma unroll
            for (int mt = 0; mt < 4; mt++)
                #pragma unroll
                for (int nt = 0; nt < 4; nt++)
                    MMA_F16(acc[mt][nt], a[mt], b[nt]);
        }
    }

    // ---- epilogue 1: store Y
    #pragma unroll
    for (int mt = 0; mt < 4; mt++) {
        #pragma unroll
        for (int nt = 0; nt < 4; nt++) {
            const int row = block_b + warp_m * 64 + mt * 16 + g;
            const int col = block_o + warp_n * 32 + nt * 8 + 2 * tig;
            float2 lo = make_float2(acc[mt][nt][0], acc[mt][nt][1]);
            float2 hi = make_float2(acc[mt][nt][2], acc[mt][nt][3]);
            *reinterpret_cast<float2*>(Y + (size_t)row * OUTF + col) = lo;
            *reinterpret_cast<float2*>(Y + (size_t)(row + 8) * OUTF + col) = hi;
        }
    }

    // ---- epilogue 2: BN partial stats for this 128-row block
    float csum[4][2], csq[4][2];
    #pragma unroll
    for (int nt = 0; nt < 4; nt++)
        #pragma unroll
        for (int c = 0; c < 2; c++) {
            float s0 = 0.0f, q0 = 0.0f;
            #pragma unroll
            for (int mt = 0; mt < 4; mt++) {
                const float vlo = acc[mt][nt][c];
                const float vhi = acc[mt][nt][c + 2];
                s0 += vlo + vhi;
                q0 = fmaf(vlo, vlo, q0);
                q0 = fmaf(vhi, vhi, q0);
            }
            csum[nt][c] = s0;
            csq[nt][c] = q0;
        }
    #pragma unroll
    for (int d = 4; d <= 16; d <<= 1) {
        #pragma unroll
        for (int nt = 0; nt < 4; nt++)
            #pragma unroll
            for (int c = 0; c < 2; c++) {
                csum[nt][c] += __shfl_xor_sync(0xFFFFFFFFu, csum[nt][c], d);
                csq[nt][c]  += __shfl_xor_sync(0xFFFFFFFFu, csq[nt][c], d);
            }
    }
    float* red_sum = reinterpret_cast<float*>(sm);          // [2][128]
    float* red_sq  = reinterpret_cast<float*>(sm) + 256;    // [2][128]
    __syncthreads();
    if (g == 0) {
        #pragma unroll
        for (int nt = 0; nt < 4; nt++)
            #pragma unroll
            for (int c = 0; c < 2; c++) {
                const int col = warp_n * 32 + nt * 8 + 2 * tig + c;
                red_sum[warp_m * 128 + col] = csum[nt][c];
                red_sq [warp_m * 128 + col] = csq[nt][c];
            }
    }
    __syncthreads();
    if (tid < 128) {
        g_psum[blockIdx.y][block_o + tid]   = red_sum[tid] + red_sum[128 + tid];
        g_psqsum[blockIdx.y][block_o + tid] = red_sq[tid]  + red_sq[128 + tid];
    }
}

// ---------------------------------------------------------------------------
// BN finalize + apply
// ---------------------------------------------------------------------------
__global__ __launch_bounds__(256)
void bn_finalize_kernel(const float* __restrict__ gamma,
                        const float* __restrict__ beta)
{
    const int o = blockIdx.x * 256 + threadIdx.x;
    float S = 0.0f, SS = 0.0f;
    #pragma unroll
    for (int i = 0; i < 32; i++) { S += g_psum[i][o]; SS += g_psqsum[i][o]; }
    const float inv_n = 1.0f / (float)BATCH;
    const float mean = S * inv_n;
    const float var  = SS * inv_n - mean * mean;
    const float rstd = rsqrtf(var + BN_EPS);
    const float sc = rstd * gamma[o];
    g_scale[o] = sc;
    g_shift[o] = fmaf(-mean, sc, beta[o]);
}

__global__ __launch_bounds__(256)
void bn_apply_kernel(float* __restrict__ Y)
{
    const int idx = blockIdx.x * blockDim.x + threadIdx.x;
    float4 v = reinterpret_cast<float4*>(Y)[idx];
    const int col = (idx & 255) * 4;
    v.x = fmaf(v.x, g_scale[col + 0], g_shift[col + 0]);
    v.y = fmaf(v.y, g_scale[col + 1], g_shift[col + 1]);
    v.z = fmaf(v.z, g_scale[col + 2], g_shift[col + 2]);
    v.w = fmaf(v.w, g_scale[col + 3], g_shift[col + 3]);
    reinterpret_cast<float4*>(Y)[idx] = v;
}

// ---------------------------------------------------------------------------
// Launcher. Inputs: x, c1, c2, c3, bias(skipped: cancels under BN), gamma, beta
// ---------------------------------------------------------------------------
extern "C" void kernel_launch(void* const* d_in, const int* in_sizes, int n_in,
                              void* d_out, int out_size)
{
    (void)in_sizes; (void)n_in; (void)out_size;
    const float* x     = (const float*)d_in[0];
    const float* c1    = (const float*)d_in[1];
    const float* c2    = (const float*)d_in[2];
    const float* c3    = (const float*)d_in[3];
    const float* gamma = (const float*)d_in[5];
    const float* beta  = (const float*)d_in[6];
    float* y = (float*)d_out;

    cudaFuncSetAttribute(poly_mma_kernel,
                         cudaFuncAttributeMaxDynamicSharedMemorySize, SMEM_BYTES);

    pack_x_kernel<<<(BATCH * INF / 4) / 256, 256>>>(x);           // 4096 blocks
    pack_c_kernel<<<(OUTF * INF / 4) / 256, 256>>>(c1, c2, c3);   // 1024 blocks

    {
        dim3 grid(OUTF / TILE_N, BATCH / TILE_M);   // (8, 32) = 256 CTAs
        poly_mma_kernel<<<grid, 256, SMEM_BYTES>>>(y);
    }
    bn_finalize_kernel<<<OUTF / 256, 256>>>(gamma, beta);
    {
        const int total_f4 = (BATCH * OUTF) / 4;
        bn_apply_kernel<<<total_f4 / 256, 256>>>(y);
    }
}

// round 9
// speedup vs baseline: 6.3073x; 1.2679x over previous
#include <cuda_runtime.h>
#include <cuda_fp16.h>
#include <cstdint>
#include <math.h>

// Problem constants: B=4096, OUT=1024, IN=1024
#define BATCH 4096
#define OUTF  1024
#define INF   1024
#define KTOT  3072            // 3 * INF (x | x^2 | x^3 concatenated on K)
#define BN_EPS 1e-5f

// ---------------------------------------------------------------------------
// Scratch (__device__ globals; no allocations allowed)
// ---------------------------------------------------------------------------
__device__ __half g_A[(size_t)BATCH * KTOT];   // 24 MB: [x | x^2 | x^3] fp16
__device__ __half g_B[(size_t)OUTF * KTOT];    //  6 MB: [c1 | c2 | c3] fp16
__device__ float g_psum[32][OUTF];
__device__ float g_psqsum[32][OUTF];
__device__ float g_scale[OUTF];
__device__ float g_shift[OUTF];

// ---------------------------------------------------------------------------
// Baseline-PTX helpers (sm_80 features only: harness compiles via compute_103)
// ---------------------------------------------------------------------------
__device__ __forceinline__ uint32_t smem_u32(const void* p) {
    uint32_t a;
    asm("{ .reg .u64 t; cvta.to.shared.u64 t, %1; cvt.u32.u64 %0, t; }" : "=r"(a) : "l"(p));
    return a;
}
__device__ __forceinline__ void cp16(uint32_t dst, const void* src) {
    asm volatile("cp.async.cg.shared.global [%0], [%1], 16;" :: "r"(dst), "l"(src));
}
__device__ __forceinline__ uint32_t pack_h2(float lo, float hi) {
    __half2 h = __floats2half2_rn(lo, hi);
    return *reinterpret_cast<uint32_t*>(&h);
}

// m16n8k16 fp16 tensor-core MMA (sm_80 baseline PTX), fp32 accumulate
#define MMA_F16(d, a, b) \
    asm volatile("mma.sync.aligned.m16n8k16.row.col.f32.f16.f16.f32 " \
        "{%0,%1,%2,%3}, {%4,%5,%6,%7}, {%8,%9}, {%0,%1,%2,%3};" \
        : "+f"((d)[0]), "+f"((d)[1]), "+f"((d)[2]), "+f"((d)[3]) \
        : "r"((a)[0]), "r"((a)[1]), "r"((a)[2]), "r"((a)[3]), \
          "r"((b)[0]), "r"((b)[1]))

// ldmatrix m8n8.x4 (sm_75+ baseline PTX)
#define LDSM_X4(r0, r1, r2, r3, addr) \
    asm volatile("ldmatrix.sync.aligned.m8n8.x4.shared.b16 {%0,%1,%2,%3}, [%4];" \
        : "=r"(r0), "=r"(r1), "=r"(r2), "=r"(r3) : "r"(addr))

// ---------------------------------------------------------------------------
// Pre-pass 1: pack A = [x | x^2 | x^3] fp16 (x^2, x^3 in fp32 then cvt)
// ---------------------------------------------------------------------------
__global__ __launch_bounds__(256)
void pack_x_kernel(const float* __restrict__ X)
{
    const int idx = blockIdx.x * 256 + threadIdx.x;       // 0 .. B*IN/4-1
    const int b  = idx >> 8;
    const int k4 = (idx & 255) * 4;
    const float4 v = *reinterpret_cast<const float4*>(X + (size_t)b * INF + k4);
    float4 s, c;
    s.x = v.x * v.x; s.y = v.y * v.y; s.z = v.z * v.z; s.w = v.w * v.w;
    c.x = s.x * v.x; c.y = s.y * v.y; c.z = s.z * v.z; c.w = s.w * v.w;
    __half* rowp = g_A + (size_t)b * KTOT;
    uint2 h;
    h.x = pack_h2(v.x, v.y); h.y = pack_h2(v.z, v.w);
    *reinterpret_cast<uint2*>(rowp + k4) = h;
    h.x = pack_h2(s.x, s.y); h.y = pack_h2(s.z, s.w);
    *reinterpret_cast<uint2*>(rowp + INF + k4) = h;
    h.x = pack_h2(c.x, c.y); h.y = pack_h2(c.z, c.w);
    *reinterpret_cast<uint2*>(rowp + 2 * INF + k4) = h;
}

// ---------------------------------------------------------------------------
// Pre-pass 2: pack B = [c1 | c2 | c3] fp16
// ---------------------------------------------------------------------------
__global__ __launch_bounds__(256)
void pack_c_kernel(const float* __restrict__ C1,
                   const float* __restrict__ C2,
                   const float* __restrict__ C3)
{
    const int idx = blockIdx.x * 256 + threadIdx.x;       // 0 .. OUT*IN/4-1
    const int o  = idx >> 8;
    const int k4 = (idx & 255) * 4;
    const size_t src = (size_t)o * INF + k4;
    __half* rowp = g_B + (size_t)o * KTOT;
    float4 v; uint2 h;
    v = *reinterpret_cast<const float4*>(C1 + src);
    h.x = pack_h2(v.x, v.y); h.y = pack_h2(v.z, v.w);
    *reinterpret_cast<uint2*>(rowp + k4) = h;
    v = *reinterpret_cast<const float4*>(C2 + src);
    h.x = pack_h2(v.x, v.y); h.y = pack_h2(v.z, v.w);
    *reinterpret_cast<uint2*>(rowp + INF + k4) = h;
    v = *reinterpret_cast<const float4*>(C3 + src);
    h.x = pack_h2(v.x, v.y); h.y = pack_h2(v.z, v.w);
    *reinterpret_cast<uint2*>(rowp + 2 * INF + k4) = h;
}

// ---------------------------------------------------------------------------
// fp16 GEMM  Y = A_packed @ B_packed^T  (M=4096, N=1024, K=3072)
// + fused BN partial stats. CTA 128x128, 8 warps (2m x 4n), warp tile 64x32.
// K chunks of 32, 4-stage cp.async pipeline, ldmatrix.x4 fragment loads.
// ---------------------------------------------------------------------------
#define TILE_M 128
#define TILE_N 128
#define KCH    32
#define NCHUNK (KTOT / KCH)        // 96
#define NSTAGE 4
#define RBB    80                  // bytes per smem row (64 data + 16 pad)
#define MATB   (128 * RBB)         // 10240 B per matrix tile
#define STAGEB (2 * MATB)          // 20480 B (A + B)
#define SMEM_BYTES (NSTAGE * STAGEB)   // 81920 B

__global__ __launch_bounds__(256, 2)
void poly_mma_kernel(float* __restrict__ Y)
{
    extern __shared__ char sm[];
    const uint32_t smbase = smem_u32(sm);

    const int tid  = threadIdx.x;
    const int wid  = tid >> 5;
    const int lane = tid & 31;
    const int g    = lane >> 2;      // 0..7
    const int tig  = lane & 3;       // 0..3
    const int warp_m = wid >> 2;     // 0..1
    const int warp_n = wid & 3;      // 0..3

    const int block_o = blockIdx.x * TILE_N;
    const int block_b = blockIdx.y * TILE_M;

    // ldmatrix per-lane address components (quad -> matrix slot)
    const int quad = lane >> 3;      // 0..3
    const int rq   = lane & 7;       // 0..7
    // A: matrices = (rows+0,k-lo)(rows+8,k-lo)(rows+0,k-hi)(rows+8,k-hi)
    const uint32_t a_lane_off = (uint32_t)((((quad & 1) * 8) + rq) * RBB + (quad >> 1) * 16);
    // B: matrices = (n+0,k-lo)(n+0,k-hi)(n+8,k-lo)(n+8,k-hi)
    const uint32_t b_lane_off = (uint32_t)((((quad >> 1) * 8) + rq) * RBB + (quad & 1) * 16);

    // cp.async geometry: 128 rows x 64 B per matrix; thread -> row tid>>1
    const int crow = tid >> 1;
    const int choff = (tid & 1) * 16;                 // halves offset in row
    const __half* srcA = g_A + (size_t)(block_b + crow) * KTOT + choff;
    const __half* srcB = g_B + (size_t)(block_o + crow) * KTOT + choff;
    const uint32_t cdst = (uint32_t)(crow * RBB + (tid & 1) * 32);

    float acc[4][4][4];
    #pragma unroll
    for (int mt = 0; mt < 4; mt++)
        #pragma unroll
        for (int nt = 0; nt < 4; nt++)
            #pragma unroll
            for (int r = 0; r < 4; r++)
                acc[mt][nt][r] = 0.0f;

    auto stage_chunk = [&](int s) {
        if (s < NCHUNK) {
            const uint32_t base = smbase + (uint32_t)((s & 3) * STAGEB) + cdst;
            const int k0 = s * KCH;
            cp16(base,             srcA + k0);
            cp16(base + 16,        srcA + k0 + 8);
            cp16(base + MATB,      srcB + k0);
            cp16(base + MATB + 16, srcB + k0 + 8);
        }
        asm volatile("cp.async.commit_group;" ::: "memory");
    };

    stage_chunk(0);
    stage_chunk(1);
    stage_chunk(2);

    const uint32_t a_warp = (uint32_t)(warp_m * 64 * RBB) + a_lane_off;
    const uint32_t b_warp = (uint32_t)(warp_n * 32 * RBB) + b_lane_off;

    for (int s = 0; s < NCHUNK; ++s) {
        asm volatile("cp.async.wait_group 2;" ::: "memory");
        __syncthreads();

        stage_chunk(s + 3);   // refills the buffer freed by this iteration

        const uint32_t stA = smbase + (uint32_t)((s & 3) * STAGEB);
        const uint32_t stB = stA + MATB;

        #pragma unroll
        for (int kk = 0; kk < 2; kk++) {
            const uint32_t kb = (uint32_t)(kk * 32);

            uint32_t a[4][4];
            #pragma unroll
            for (int mt = 0; mt < 4; mt++)
                LDSM_X4(a[mt][0], a[mt][1], a[mt][2], a[mt][3],
                        stA + a_warp + (uint32_t)(mt * 16 * RBB) + kb);

            uint32_t b[4][2];
            #pragma unroll
            for (int p = 0; p < 2; p++)
                LDSM_X4(b[2 * p][0], b[2 * p][1], b[2 * p + 1][0], b[2 * p + 1][1],
                        stB + b_warp + (uint32_t)(p * 16 * RBB) + kb);

            #pragma unroll
            for (int mt = 0; mt < 4; mt++)
                #pragma unroll
                for (int nt = 0; nt < 4; nt++)
                    MMA_F16(acc[mt][nt], a[mt], b[nt]);
        }
    }

    // ---- epilogue 1: store Y
    #pragma unroll
    for (int mt = 0; mt < 4; mt++) {
        #pragma unroll
        for (int nt = 0; nt < 4; nt++) {
            const int row = block_b + warp_m * 64 + mt * 16 + g;
            const int col = block_o + warp_n * 32 + nt * 8 + 2 * tig;
            float2 lo = make_float2(acc[mt][nt][0], acc[mt][nt][1]);
            float2 hi = make_float2(acc[mt][nt][2], acc[mt][nt][3]);
            *reinterpret_cast<float2*>(Y + (size_t)row * OUTF + col) = lo;
            *reinterpret_cast<float2*>(Y + (size_t)(row + 8) * OUTF + col) = hi;
        }
    }

    // ---- epilogue 2: BN partial stats for this 128-row block
    float csum[4][2], csq[4][2];
    #pragma unroll
    for (int nt = 0; nt < 4; nt++)
        #pragma unroll
        for (int c = 0; c < 2; c++) {
            float s0 = 0.0f, q0 = 0.0f;
            #pragma unroll
            for (int mt = 0; mt < 4; mt++) {
                const float vlo = acc[mt][nt][c];
                const float vhi = acc[mt][nt][c + 2];
                s0 += vlo + vhi;
                q0 = fmaf(vlo, vlo, q0);
                q0 = fmaf(vhi, vhi, q0);
            }
            csum[nt][c] = s0;
            csq[nt][c] = q0;
        }
    #pragma unroll
    for (int d = 4; d <= 16; d <<= 1) {
        #pragma unroll
        for (int nt = 0; nt < 4; nt++)
            #pragma unroll
            for (int c = 0; c < 2; c++) {
                csum[nt][c] += __shfl_xor_sync(0xFFFFFFFFu, csum[nt][c], d);
                csq[nt][c]  += __shfl_xor_sync(0xFFFFFFFFu, csq[nt][c], d);
            }
    }
    float* red_sum = reinterpret_cast<float*>(sm);          // [2][128]
    float* red_sq  = reinterpret_cast<float*>(sm) + 256;    // [2][128]
    __syncthreads();
    if (g == 0) {
        #pragma unroll
        for (int nt = 0; nt < 4; nt++)
            #pragma unroll
            for (int c = 0; c < 2; c++) {
                const int col = warp_n * 32 + nt * 8 + 2 * tig + c;
                red_sum[warp_m * 128 + col] = csum[nt][c];
                red_sq [warp_m * 128 + col] = csq[nt][c];
            }
    }
    __syncthreads();
    if (tid < 128) {
        g_psum[blockIdx.y][block_o + tid]   = red_sum[tid] + red_sum[128 + tid];
        g_psqsum[blockIdx.y][block_o + tid] = red_sq[tid]  + red_sq[128 + tid];
    }
}

// ---------------------------------------------------------------------------
// BN finalize: 32 CTAs, 8 threads per column (4 partials each) + shfl reduce
// ---------------------------------------------------------------------------
__global__ __launch_bounds__(256)
void bn_finalize_kernel(const float* __restrict__ gamma,
                        const float* __restrict__ beta)
{
    const int o = blockIdx.x * 32 + (threadIdx.x >> 3);
    const int p = threadIdx.x & 7;
    float S = 0.0f, SS = 0.0f;
    #pragma unroll
    for (int i = 0; i < 4; i++) {
        S  += g_psum[p * 4 + i][o];
        SS += g_psqsum[p * 4 + i][o];
    }
    #pragma unroll
    for (int d = 1; d < 8; d <<= 1) {
        S  += __shfl_xor_sync(0xFFFFFFFFu, S, d);
        SS += __shfl_xor_sync(0xFFFFFFFFu, SS, d);
    }
    if (p == 0) {
        const float inv_n = 1.0f / (float)BATCH;
        const float mean = S * inv_n;
        const float var  = SS * inv_n - mean * mean;
        const float rstd = rsqrtf(var + BN_EPS);
        const float sc = rstd * gamma[o];
        g_scale[o] = sc;
        g_shift[o] = fmaf(-mean, sc, beta[o]);
    }
}

// ---------------------------------------------------------------------------
// BN apply in place: 4 float4 per thread, same column (1024-row stride)
// ---------------------------------------------------------------------------
#define APPLY_Q (BATCH * OUTF / 16)   // 1,048,576/4 float4s per j-pass

__global__ __launch_bounds__(256)
void bn_apply_kernel(float* __restrict__ Y)
{
    const int idx = blockIdx.x * blockDim.x + threadIdx.x;   // 0 .. APPLY_Q-1
    const int col = (idx & 255) * 4;
    const float4 sc = *reinterpret_cast<const float4*>(&g_scale[col]);
    const float4 sh = *reinterpret_cast<const float4*>(&g_shift[col]);
    #pragma unroll
    for (int j = 0; j < 4; j++) {
        float4 v = reinterpret_cast<float4*>(Y)[idx + j * APPLY_Q];
        v.x = fmaf(v.x, sc.x, sh.x);
        v.y = fmaf(v.y, sc.y, sh.y);
        v.z = fmaf(v.z, sc.z, sh.z);
        v.w = fmaf(v.w, sc.w, sh.w);
        reinterpret_cast<float4*>(Y)[idx + j * APPLY_Q] = v;
    }
}

// ---------------------------------------------------------------------------
// Launcher. Inputs: x, c1, c2, c3, bias(skipped: cancels under BN), gamma, beta
// ---------------------------------------------------------------------------
extern "C" void kernel_launch(void* const* d_in, const int* in_sizes, int n_in,
                              void* d_out, int out_size)
{
    (void)in_sizes; (void)n_in; (void)out_size;
    const float* x     = (const float*)d_in[0];
    const float* c1    = (const float*)d_in[1];
    const float* c2    = (const float*)d_in[2];
    const float* c3    = (const float*)d_in[3];
    const float* gamma = (const float*)d_in[5];
    const float* beta  = (const float*)d_in[6];
    float* y = (float*)d_out;

    cudaFuncSetAttribute(poly_mma_kernel,
                         cudaFuncAttributeMaxDynamicSharedMemorySize, SMEM_BYTES);

    pack_x_kernel<<<(BATCH * INF / 4) / 256, 256>>>(x);
    pack_c_kernel<<<(OUTF * INF / 4) / 256, 256>>>(c1, c2, c3);

    {
        dim3 grid(OUTF / TILE_N, BATCH / TILE_M);   // (8, 32) = 256 CTAs
        poly_mma_kernel<<<grid, 256, SMEM_BYTES>>>(y);
    }
    bn_finalize_kernel<<<OUTF / 32, 256>>>(gamma, beta);
    bn_apply_kernel<<<APPLY_Q / 256, 256>>>(y);
}

// round 10
// speedup vs baseline: 6.4321x; 1.0198x over previous
#include <cuda_runtime.h>
#include <cuda_fp16.h>
#include <cstdint>
#include <math.h>

// Problem constants: B=4096, OUT=1024, IN=1024
#define BATCH 4096
#define OUTF  1024
#define INF   1024
#define KTOT  3072            // 3 * INF (x | x^2 | x^3 concatenated on K)
#define BN_EPS 1e-5f

// ---------------------------------------------------------------------------
// Scratch (__device__ globals; no allocations allowed)
// ---------------------------------------------------------------------------
__device__ __half g_A[(size_t)BATCH * KTOT];   // 24 MB: [x | x^2 | x^3] fp16
__device__ __half g_B[(size_t)OUTF * KTOT];    //  6 MB: [c1 | c2 | c3] fp16
__device__ float g_psum[32][OUTF];
__device__ float g_psqsum[32][OUTF];
__device__ float g_scale[OUTF];
__device__ float g_shift[OUTF];

// ---------------------------------------------------------------------------
// Baseline-PTX helpers (sm_80 features only: harness compiles via compute_103)
// ---------------------------------------------------------------------------
__device__ __forceinline__ uint32_t smem_u32(const void* p) {
    uint32_t a;
    asm("{ .reg .u64 t; cvta.to.shared.u64 t, %1; cvt.u32.u64 %0, t; }" : "=r"(a) : "l"(p));
    return a;
}
__device__ __forceinline__ void cp16(uint32_t dst, const void* src) {
    asm volatile("cp.async.cg.shared.global [%0], [%1], 16;" :: "r"(dst), "l"(src));
}
__device__ __forceinline__ uint32_t pack_h2(float lo, float hi) {
    __half2 h = __floats2half2_rn(lo, hi);
    return *reinterpret_cast<uint32_t*>(&h);
}

// m16n8k16 fp16 tensor-core MMA (sm_80 baseline PTX), fp32 accumulate
#define MMA_F16(d, a, b) \
    asm volatile("mma.sync.aligned.m16n8k16.row.col.f32.f16.f16.f32 " \
        "{%0,%1,%2,%3}, {%4,%5,%6,%7}, {%8,%9}, {%0,%1,%2,%3};" \
        : "+f"((d)[0]), "+f"((d)[1]), "+f"((d)[2]), "+f"((d)[3]) \
        : "r"((a)[0]), "r"((a)[1]), "r"((a)[2]), "r"((a)[3]), \
          "r"((b)[0]), "r"((b)[1]))

// ldmatrix m8n8.x4 (sm_75+ baseline PTX)
#define LDSM_X4(r0, r1, r2, r3, addr) \
    asm volatile("ldmatrix.sync.aligned.m8n8.x4.shared.b16 {%0,%1,%2,%3}, [%4];" \
        : "=r"(r0), "=r"(r1), "=r"(r2), "=r"(r3) : "r"(addr))

// ---------------------------------------------------------------------------
// Pre-pass (merged): pack A = [x|x^2|x^3] and B = [c1|c2|c3] as fp16.
// Blocks [0,4096) handle A; blocks [4096,5120) handle B.
// ---------------------------------------------------------------------------
__global__ __launch_bounds__(256)
void pack_kernel(const float* __restrict__ X,
                 const float* __restrict__ C1,
                 const float* __restrict__ C2,
                 const float* __restrict__ C3)
{
    if (blockIdx.x < 4096) {
        const int idx = blockIdx.x * 256 + threadIdx.x;   // 0 .. B*IN/4-1
        const int b  = idx >> 8;
        const int k4 = (idx & 255) * 4;
        const float4 v = *reinterpret_cast<const float4*>(X + (size_t)b * INF + k4);
        float4 s, c;
        s.x = v.x * v.x; s.y = v.y * v.y; s.z = v.z * v.z; s.w = v.w * v.w;
        c.x = s.x * v.x; c.y = s.y * v.y; c.z = s.z * v.z; c.w = s.w * v.w;
        __half* rowp = g_A + (size_t)b * KTOT;
        uint2 h;
        h.x = pack_h2(v.x, v.y); h.y = pack_h2(v.z, v.w);
        *reinterpret_cast<uint2*>(rowp + k4) = h;
        h.x = pack_h2(s.x, s.y); h.y = pack_h2(s.z, s.w);
        *reinterpret_cast<uint2*>(rowp + INF + k4) = h;
        h.x = pack_h2(c.x, c.y); h.y = pack_h2(c.z, c.w);
        *reinterpret_cast<uint2*>(rowp + 2 * INF + k4) = h;
    } else {
        const int idx = (blockIdx.x - 4096) * 256 + threadIdx.x;  // 0 .. OUT*IN/4-1
        const int o  = idx >> 8;
        const int k4 = (idx & 255) * 4;
        const size_t src = (size_t)o * INF + k4;
        __half* rowp = g_B + (size_t)o * KTOT;
        float4 v; uint2 h;
        v = *reinterpret_cast<const float4*>(C1 + src);
        h.x = pack_h2(v.x, v.y); h.y = pack_h2(v.z, v.w);
        *reinterpret_cast<uint2*>(rowp + k4) = h;
        v = *reinterpret_cast<const float4*>(C2 + src);
        h.x = pack_h2(v.x, v.y); h.y = pack_h2(v.z, v.w);
        *reinterpret_cast<uint2*>(rowp + INF + k4) = h;
        v = *reinterpret_cast<const float4*>(C3 + src);
        h.x = pack_h2(v.x, v.y); h.y = pack_h2(v.z, v.w);
        *reinterpret_cast<uint2*>(rowp + 2 * INF + k4) = h;
    }
}

// ---------------------------------------------------------------------------
// fp16 GEMM  Y = A_packed @ B_packed^T  (M=4096, N=1024, K=3072)
// + fused BN partial stats.
// CTA tile 128(M) x 256(N), 8 warps (2m x 4n), warp tile 64x64.
// Grid = (4, 32) = 128 CTAs -> exactly 1 CTA/SM, single balanced wave.
// K chunks of 32 halves, 4-stage cp.async pipeline, ldmatrix.x4 loads.
// Per k16 slab per warp: 8 LDSM.x4 + 32 MMA (2x the MMA:LDSM ratio of R8).
// ---------------------------------------------------------------------------
#define TILE_M 128
#define TILE_N 256
#define KCH    32
#define NCHUNK (KTOT / KCH)        // 96
#define RBB    80                  // bytes per smem row (64 data + 16 pad)
#define MATB_A (128 * RBB)         // 10240 B
#define MATB_B (256 * RBB)         // 20480 B
#define STAGEB (MATB_A + MATB_B)   // 30720 B
#define SMEM_BYTES (4 * STAGEB)    // 122880 B

__global__ __launch_bounds__(256, 1)
void poly_mma_kernel(float* __restrict__ Y)
{
    extern __shared__ char sm[];
    const uint32_t smbase = smem_u32(sm);

    const int tid  = threadIdx.x;
    const int wid  = tid >> 5;
    const int lane = tid & 31;
    const int g    = lane >> 2;      // 0..7
    const int tig  = lane & 3;       // 0..3
    const int warp_m = wid >> 2;     // 0..1  -> m base = warp_m*64
    const int warp_n = wid & 3;      // 0..3  -> n base = warp_n*64

    const int block_o = blockIdx.x * TILE_N;
    const int block_b = blockIdx.y * TILE_M;

    // ldmatrix per-lane address components (quad -> matrix slot)
    const int quad = lane >> 3;      // 0..3
    const int rq   = lane & 7;       // 0..7
    // A x4: (rows+0,k-lo)(rows+8,k-lo)(rows+0,k-hi)(rows+8,k-hi)
    const uint32_t a_lane_off = (uint32_t)((((quad & 1) * 8) + rq) * RBB + (quad >> 1) * 16);
    // B x4: (n+0,k-lo)(n+0,k-hi)(n+8,k-lo)(n+8,k-hi)
    const uint32_t b_lane_off = (uint32_t)((((quad >> 1) * 8) + rq) * RBB + (quad & 1) * 16);

    // cp.async geometry: thread -> A row tid>>1 (2 cp16), B rows tid>>1 and
    // tid>>1 + 128 (2 cp16 each). 32 contiguous bytes per (row, half).
    const int crow  = tid >> 1;
    const int choff = (tid & 1) * 16;                 // halves offset in row
    const __half* srcA  = g_A + (size_t)(block_b + crow) * KTOT + choff;
    const __half* srcB0 = g_B + (size_t)(block_o + crow) * KTOT + choff;
    const __half* srcB1 = g_B + (size_t)(block_o + crow + 128) * KTOT + choff;
    const uint32_t cdst = (uint32_t)(crow * RBB + (tid & 1) * 32);

    float acc[4][8][4];
    #pragma unroll
    for (int mt = 0; mt < 4; mt++)
        #pragma unroll
        for (int nt = 0; nt < 8; nt++)
            #pragma unroll
            for (int r = 0; r < 4; r++)
                acc[mt][nt][r] = 0.0f;

    auto stage_chunk = [&](int s) {
        if (s < NCHUNK) {
            const uint32_t base = smbase + (uint32_t)((s & 3) * STAGEB);
            const int k0 = s * KCH;
            cp16(base + cdst,      srcA + k0);
            cp16(base + cdst + 16, srcA + k0 + 8);
            const uint32_t bB = base + MATB_A;
            cp16(bB + cdst,                  srcB0 + k0);
            cp16(bB + cdst + 16,             srcB0 + k0 + 8);
            cp16(bB + cdst + 128 * RBB,      srcB1 + k0);
            cp16(bB + cdst + 128 * RBB + 16, srcB1 + k0 + 8);
        }
        asm volatile("cp.async.commit_group;" ::: "memory");
    };

    stage_chunk(0);
    stage_chunk(1);
    stage_chunk(2);

    const uint32_t a_warp = (uint32_t)(warp_m * 64 * RBB) + a_lane_off;
    const uint32_t b_warp = (uint32_t)(warp_n * 64 * RBB) + b_lane_off;

    for (int s = 0; s < NCHUNK; ++s) {
        asm volatile("cp.async.wait_group 2;" ::: "memory");
        __syncthreads();

        stage_chunk(s + 3);   // refills the buffer freed by this iteration

        const uint32_t stA = smbase + (uint32_t)((s & 3) * STAGEB);
        const uint32_t stB = stA + MATB_A;

        #pragma unroll
        for (int kk = 0; kk < 2; kk++) {
            const uint32_t kb = (uint32_t)(kk * 32);

            uint32_t a[4][4];
            #pragma unroll
            for (int mt = 0; mt < 4; mt++)
                LDSM_X4(a[mt][0], a[mt][1], a[mt][2], a[mt][3],
                        stA + a_warp + (uint32_t)(mt * 16 * RBB) + kb);

            uint32_t b[8][2];
            #pragma unroll
            for (int p = 0; p < 4; p++)
                LDSM_X4(b[2 * p][0], b[2 * p][1], b[2 * p + 1][0], b[2 * p + 1][1],
                        stB + b_warp + (uint32_t)(p * 16 * RBB) + kb);

            #pragma unroll
            for (int mt = 0; mt < 4; mt++)
                #pragma unroll
                for (int nt = 0; nt < 8; nt++)
                    MMA_F16(acc[mt][nt], a[mt], b[nt]);
        }
    }

    // ---- epilogue 1: store Y
    #pragma unroll
    for (int mt = 0; mt < 4; mt++) {
        #pragma unroll
        for (int nt = 0; nt < 8; nt++) {
            const int row = block_b + warp_m * 64 + mt * 16 + g;
            const int col = block_o + warp_n * 64 + nt * 8 + 2 * tig;
            float2 lo = make_float2(acc[mt][nt][0], acc[mt][nt][1]);
            float2 hi = make_float2(acc[mt][nt][2], acc[mt][nt][3]);
            *reinterpret_cast<float2*>(Y + (size_t)row * OUTF + col) = lo;
            *reinterpret_cast<float2*>(Y + (size_t)(row + 8) * OUTF + col) = hi;
        }
    }

    // ---- epilogue 2: BN partial stats for this 128-row block
    float csum[8][2], csq[8][2];
    #pragma unroll
    for (int nt = 0; nt < 8; nt++)
        #pragma unroll
        for (int c = 0; c < 2; c++) {
            float s0 = 0.0f, q0 = 0.0f;
            #pragma unroll
            for (int mt = 0; mt < 4; mt++) {
                const float vlo = acc[mt][nt][c];
                const float vhi = acc[mt][nt][c + 2];
                s0 += vlo + vhi;
                q0 = fmaf(vlo, vlo, q0);
                q0 = fmaf(vhi, vhi, q0);
            }
            csum[nt][c] = s0;
            csq[nt][c] = q0;
        }
    #pragma unroll
    for (int d = 4; d <= 16; d <<= 1) {
        #pragma unroll
        for (int nt = 0; nt < 8; nt++)
            #pragma unroll
            for (int c = 0; c < 2; c++) {
                csum[nt][c] += __shfl_xor_sync(0xFFFFFFFFu, csum[nt][c], d);
                csq[nt][c]  += __shfl_xor_sync(0xFFFFFFFFu, csq[nt][c], d);
            }
    }
    float* red_sum = reinterpret_cast<float*>(sm);          // [2][256]
    float* red_sq  = reinterpret_cast<float*>(sm) + 512;    // [2][256]
    __syncthreads();
    if (g == 0) {
        #pragma unroll
        for (int nt = 0; nt < 8; nt++)
            #pragma unroll
            for (int c = 0; c < 2; c++) {
                const int col = warp_n * 64 + nt * 8 + 2 * tig + c;
                red_sum[warp_m * 256 + col] = csum[nt][c];
                red_sq [warp_m * 256 + col] = csq[nt][c];
            }
    }
    __syncthreads();
    {
        const int col = tid;   // 0..255
        g_psum[blockIdx.y][block_o + col]   = red_sum[col] + red_sum[256 + col];
        g_psqsum[blockIdx.y][block_o + col] = red_sq[col]  + red_sq[256 + col];
    }
}

// ---------------------------------------------------------------------------
// BN finalize: 8 threads per column (4 partials each) + shfl reduce
// ---------------------------------------------------------------------------
__global__ __launch_bounds__(256)
void bn_finalize_kernel(const float* __restrict__ gamma,
                        const float* __restrict__ beta)
{
    const int o = blockIdx.x * 32 + (threadIdx.x >> 3);
    const int p = threadIdx.x & 7;
    float S = 0.0f, SS = 0.0f;
    #pragma unroll
    for (int i = 0; i < 4; i++) {
        S  += g_psum[p * 4 + i][o];
        SS += g_psqsum[p * 4 + i][o];
    }
    #pragma unroll
    for (int d = 1; d < 8; d <<= 1) {
        S  += __shfl_xor_sync(0xFFFFFFFFu, S, d);
        SS += __shfl_xor_sync(0xFFFFFFFFu, SS, d);
    }
    if (p == 0) {
        const float inv_n = 1.0f / (float)BATCH;
        const float mean = S * inv_n;
        const float var  = SS * inv_n - mean * mean;
        const float rstd = rsqrtf(var + BN_EPS);
        const float sc = rstd * gamma[o];
        g_scale[o] = sc;
        g_shift[o] = fmaf(-mean, sc, beta[o]);
    }
}

// ---------------------------------------------------------------------------
// BN apply in place: 4 float4 per thread, same column (1024-row stride)
// ---------------------------------------------------------------------------
#define APPLY_Q (BATCH * OUTF / 16)

__global__ __launch_bounds__(256)
void bn_apply_kernel(float* __restrict__ Y)
{
    const int idx = blockIdx.x * blockDim.x + threadIdx.x;   // 0 .. APPLY_Q-1
    const int col = (idx & 255) * 4;
    const float4 sc = *reinterpret_cast<const float4*>(&g_scale[col]);
    const float4 sh = *reinterpret_cast<const float4*>(&g_shift[col]);
    #pragma unroll
    for (int j = 0; j < 4; j++) {
        float4 v = reinterpret_cast<float4*>(Y)[idx + j * APPLY_Q];
        v.x = fmaf(v.x, sc.x, sh.x);
        v.y = fmaf(v.y, sc.y, sh.y);
        v.z = fmaf(v.z, sc.z, sh.z);
        v.w = fmaf(v.w, sc.w, sh.w);
        reinterpret_cast<float4*>(Y)[idx + j * APPLY_Q] = v;
    }
}

// ---------------------------------------------------------------------------
// Launcher. Inputs: x, c1, c2, c3, bias(skipped: cancels under BN), gamma, beta
// ---------------------------------------------------------------------------
extern "C" void kernel_launch(void* const* d_in, const int* in_sizes, int n_in,
                              void* d_out, int out_size)
{
    (void)in_sizes; (void)n_in; (void)out_size;
    const float* x     = (const float*)d_in[0];
    const float* c1    = (const float*)d_in[1];
    const float* c2    = (const float*)d_in[2];
    const float* c3    = (const float*)d_in[3];
    const float* gamma = (const float*)d_in[5];
    const float* beta  = (const float*)d_in[6];
    float* y = (float*)d_out;

    cudaFuncSetAttribute(poly_mma_kernel,
                         cudaFuncAttributeMaxDynamicSharedMemorySize, SMEM_BYTES);

    pack_kernel<<<4096 + 1024, 256>>>(x, c1, c2, c3);

    {
        dim3 grid(OUTF / TILE_N, BATCH / TILE_M);   // (4, 32) = 128 CTAs
        poly_mma_kernel<<<grid, 256, SMEM_BYTES>>>(y);
    }
    bn_finalize_kernel<<<OUTF / 32, 256>>>(gamma, beta);
    bn_apply_kernel<<<APPLY_Q / 256, 256>>>(y);
}

// round 11
// speedup vs baseline: 6.5375x; 1.0164x over previous
#include <cuda_runtime.h>
#include <cuda_fp16.h>
#include <cstdint>
#include <math.h>

// Problem constants: B=4096, OUT=1024, IN=1024
#define BATCH 4096
#define OUTF  1024
#define INF   1024
#define KTOT  3072            // 3 * INF (x | x^2 | x^3 concatenated on K)
#define BN_EPS 1e-5f
#define GRID_CTAS 128

// ---------------------------------------------------------------------------
// Scratch (__device__ globals; no allocations allowed)
// ---------------------------------------------------------------------------
__device__ __half g_A[(size_t)BATCH * KTOT];   // 24 MB: [x | x^2 | x^3] fp16
__device__ __half g_B[(size_t)OUTF * KTOT];    //  6 MB: [c1 | c2 | c3] fp16
__device__ float g_psum[32][OUTF];
__device__ float g_psqsum[32][OUTF];
__device__ unsigned int g_bar = 0;             // monotonic grid-barrier ticket

// ---------------------------------------------------------------------------
// Baseline-PTX helpers (sm_80 features only: harness compiles via compute_103)
// ---------------------------------------------------------------------------
__device__ __forceinline__ uint32_t smem_u32(const void* p) {
    uint32_t a;
    asm("{ .reg .u64 t; cvta.to.shared.u64 t, %1; cvt.u32.u64 %0, t; }" : "=r"(a) : "l"(p));
    return a;
}
__device__ __forceinline__ void cp16(uint32_t dst, const void* src) {
    asm volatile("cp.async.cg.shared.global [%0], [%1], 16;" :: "r"(dst), "l"(src));
}
__device__ __forceinline__ uint32_t pack_h2(float lo, float hi) {
    __half2 h = __floats2half2_rn(lo, hi);
    return *reinterpret_cast<uint32_t*>(&h);
}
__device__ __forceinline__ unsigned int ld_acquire_gpu(const unsigned int* p) {
    unsigned int v;
    asm volatile("ld.acquire.gpu.u32 %0, [%1];" : "=r"(v) : "l"(p) : "memory");
    return v;
}

// m16n8k16 fp16 tensor-core MMA (sm_80 baseline PTX), fp32 accumulate
#define MMA_F16(d, a, b) \
    asm volatile("mma.sync.aligned.m16n8k16.row.col.f32.f16.f16.f32 " \
        "{%0,%1,%2,%3}, {%4,%5,%6,%7}, {%8,%9}, {%0,%1,%2,%3};" \
        : "+f"((d)[0]), "+f"((d)[1]), "+f"((d)[2]), "+f"((d)[3]) \
        : "r"((a)[0]), "r"((a)[1]), "r"((a)[2]), "r"((a)[3]), \
          "r"((b)[0]), "r"((b)[1]))

// ldmatrix m8n8.x4 (sm_75+ baseline PTX)
#define LDSM_X4(r0, r1, r2, r3, addr) \
    asm volatile("ldmatrix.sync.aligned.m8n8.x4.shared.b16 {%0,%1,%2,%3}, [%4];" \
        : "=r"(r0), "=r"(r1), "=r"(r2), "=r"(r3) : "r"(addr))

// ---------------------------------------------------------------------------
// Pre-pass: pack A = [x|x^2|x^3] and B = [c1|c2|c3] as fp16.
// Blocks [0,4096) -> A; [4096,5120) -> B.
// ---------------------------------------------------------------------------
__global__ __launch_bounds__(256)
void pack_kernel(const float* __restrict__ X,
                 const float* __restrict__ C1,
                 const float* __restrict__ C2,
                 const float* __restrict__ C3)
{
    if (blockIdx.x < 4096) {
        const int idx = blockIdx.x * 256 + threadIdx.x;
        const int b  = idx >> 8;
        const int k4 = (idx & 255) * 4;
        const float4 v = *reinterpret_cast<const float4*>(X + (size_t)b * INF + k4);
        float4 s, c;
        s.x = v.x * v.x; s.y = v.y * v.y; s.z = v.z * v.z; s.w = v.w * v.w;
        c.x = s.x * v.x; c.y = s.y * v.y; c.z = s.z * v.z; c.w = s.w * v.w;
        __half* rowp = g_A + (size_t)b * KTOT;
        uint2 h;
        h.x = pack_h2(v.x, v.y); h.y = pack_h2(v.z, v.w);
        *reinterpret_cast<uint2*>(rowp + k4) = h;
        h.x = pack_h2(s.x, s.y); h.y = pack_h2(s.z, s.w);
        *reinterpret_cast<uint2*>(rowp + INF + k4) = h;
        h.x = pack_h2(c.x, c.y); h.y = pack_h2(c.z, c.w);
        *reinterpret_cast<uint2*>(rowp + 2 * INF + k4) = h;
    } else {
        const int idx = (blockIdx.x - 4096) * 256 + threadIdx.x;
        const int o  = idx >> 8;
        const int k4 = (idx & 255) * 4;
        const size_t src = (size_t)o * INF + k4;
        __half* rowp = g_B + (size_t)o * KTOT;
        float4 v; uint2 h;
        v = *reinterpret_cast<const float4*>(C1 + src);
        h.x = pack_h2(v.x, v.y); h.y = pack_h2(v.z, v.w);
        *reinterpret_cast<uint2*>(rowp + k4) = h;
        v = *reinterpret_cast<const float4*>(C2 + src);
        h.x = pack_h2(v.x, v.y); h.y = pack_h2(v.z, v.w);
        *reinterpret_cast<uint2*>(rowp + INF + k4) = h;
        v = *reinterpret_cast<const float4*>(C3 + src);
        h.x = pack_h2(v.x, v.y); h.y = pack_h2(v.z, v.w);
        *reinterpret_cast<uint2*>(rowp + 2 * INF + k4) = h;
    }
}

// ---------------------------------------------------------------------------
// Fully fused: fp16 GEMM (M=4096,N=1024,K=3072) + BN stats + grid barrier +
// BN finalize + normalized store. Grid = (4,32) = 128 CTAs at 1 CTA/SM ->
// all CTAs co-resident (128 <= 148 SMs): software grid barrier is safe.
// CTA tile 128x256, 8 warps (2m x 4n), warp tile 64x64, 4-stage cp.async,
// ldmatrix.x4 fragment loads.
// ---------------------------------------------------------------------------
#define TILE_M 128
#define TILE_N 256
#define KCH    32
#define NCHUNK (KTOT / KCH)        // 96
#define RBB    80                  // bytes per smem row (64 data + 16 pad)
#define MATB_A (128 * RBB)         // 10240 B
#define MATB_B (256 * RBB)         // 20480 B
#define STAGEB (MATB_A + MATB_B)   // 30720 B
#define SMEM_BYTES (4 * STAGEB)    // 122880 B

__global__ __launch_bounds__(256, 1)
void poly_mma_bn_kernel(float* __restrict__ Y,
                        const float* __restrict__ gamma,
                        const float* __restrict__ beta)
{
    extern __shared__ char sm[];
    const uint32_t smbase = smem_u32(sm);

    const int tid  = threadIdx.x;
    const int wid  = tid >> 5;
    const int lane = tid & 31;
    const int g    = lane >> 2;      // 0..7
    const int tig  = lane & 3;       // 0..3
    const int warp_m = wid >> 2;     // 0..1  -> m base = warp_m*64
    const int warp_n = wid & 3;      // 0..3  -> n base = warp_n*64

    const int block_o = blockIdx.x * TILE_N;
    const int block_b = blockIdx.y * TILE_M;

    // ldmatrix per-lane address components
    const int quad = lane >> 3;
    const int rq   = lane & 7;
    const uint32_t a_lane_off = (uint32_t)((((quad & 1) * 8) + rq) * RBB + (quad >> 1) * 16);
    const uint32_t b_lane_off = (uint32_t)((((quad >> 1) * 8) + rq) * RBB + (quad & 1) * 16);

    // cp.async geometry
    const int crow  = tid >> 1;
    const int choff = (tid & 1) * 16;
    const __half* srcA  = g_A + (size_t)(block_b + crow) * KTOT + choff;
    const __half* srcB0 = g_B + (size_t)(block_o + crow) * KTOT + choff;
    const __half* srcB1 = g_B + (size_t)(block_o + crow + 128) * KTOT + choff;
    const uint32_t cdst = (uint32_t)(crow * RBB + (tid & 1) * 32);

    float acc[4][8][4];
    #pragma unroll
    for (int mt = 0; mt < 4; mt++)
        #pragma unroll
        for (int nt = 0; nt < 8; nt++)
            #pragma unroll
            for (int r = 0; r < 4; r++)
                acc[mt][nt][r] = 0.0f;

    auto stage_chunk = [&](int s) {
        if (s < NCHUNK) {
            const uint32_t base = smbase + (uint32_t)((s & 3) * STAGEB);
            const int k0 = s * KCH;
            cp16(base + cdst,      srcA + k0);
            cp16(base + cdst + 16, srcA + k0 + 8);
            const uint32_t bB = base + MATB_A;
            cp16(bB + cdst,                  srcB0 + k0);
            cp16(bB + cdst + 16,             srcB0 + k0 + 8);
            cp16(bB + cdst + 128 * RBB,      srcB1 + k0);
            cp16(bB + cdst + 128 * RBB + 16, srcB1 + k0 + 8);
        }
        asm volatile("cp.async.commit_group;" ::: "memory");
    };

    stage_chunk(0);
    stage_chunk(1);
    stage_chunk(2);

    const uint32_t a_warp = (uint32_t)(warp_m * 64 * RBB) + a_lane_off;
    const uint32_t b_warp = (uint32_t)(warp_n * 64 * RBB) + b_lane_off;

    for (int s = 0; s < NCHUNK; ++s) {
        asm volatile("cp.async.wait_group 2;" ::: "memory");
        __syncthreads();

        stage_chunk(s + 3);

        const uint32_t stA = smbase + (uint32_t)((s & 3) * STAGEB);
        const uint32_t stB = stA + MATB_A;

        #pragma unroll
        for (int kk = 0; kk < 2; kk++) {
            const uint32_t kb = (uint32_t)(kk * 32);

            uint32_t a[4][4];
            #pragma unroll
            for (int mt = 0; mt < 4; mt++)
                LDSM_X4(a[mt][0], a[mt][1], a[mt][2], a[mt][3],
                        stA + a_warp + (uint32_t)(mt * 16 * RBB) + kb);

            uint32_t b[8][2];
            #pragma unroll
            for (int p = 0; p < 4; p++)
                LDSM_X4(b[2 * p][0], b[2 * p][1], b[2 * p + 1][0], b[2 * p + 1][1],
                        stB + b_warp + (uint32_t)(p * 16 * RBB) + kb);

            #pragma unroll
            for (int mt = 0; mt < 4; mt++)
                #pragma unroll
                for (int nt = 0; nt < 8; nt++)
                    MMA_F16(acc[mt][nt], a[mt], b[nt]);
        }
    }

    // ---- phase 1: BN partial stats for this 128-row block (registers only)
    float csum[8][2], csq[8][2];
    #pragma unroll
    for (int nt = 0; nt < 8; nt++)
        #pragma unroll
        for (int c = 0; c < 2; c++) {
            float s0 = 0.0f, q0 = 0.0f;
            #pragma unroll
            for (int mt = 0; mt < 4; mt++) {
                const float vlo = acc[mt][nt][c];
                const float vhi = acc[mt][nt][c + 2];
                s0 += vlo + vhi;
                q0 = fmaf(vlo, vlo, q0);
                q0 = fmaf(vhi, vhi, q0);
            }
            csum[nt][c] = s0;
            csq[nt][c] = q0;
        }
    #pragma unroll
    for (int d = 4; d <= 16; d <<= 1) {
        #pragma unroll
        for (int nt = 0; nt < 8; nt++)
            #pragma unroll
            for (int c = 0; c < 2; c++) {
                csum[nt][c] += __shfl_xor_sync(0xFFFFFFFFu, csum[nt][c], d);
                csq[nt][c]  += __shfl_xor_sync(0xFFFFFFFFu, csq[nt][c], d);
            }
    }
    float* red_sum = reinterpret_cast<float*>(sm);          // [2][256]
    float* red_sq  = reinterpret_cast<float*>(sm) + 512;    // [2][256]
    __syncthreads();
    if (g == 0) {
        #pragma unroll
        for (int nt = 0; nt < 8; nt++)
            #pragma unroll
            for (int c = 0; c < 2; c++) {
                const int col = warp_n * 64 + nt * 8 + 2 * tig + c;
                red_sum[warp_m * 256 + col] = csum[nt][c];
                red_sq [warp_m * 256 + col] = csq[nt][c];
            }
    }
    __syncthreads();
    {
        const int col = tid;
        g_psum[blockIdx.y][block_o + col]   = red_sum[col] + red_sum[256 + col];
        g_psqsum[blockIdx.y][block_o + col] = red_sq[col]  + red_sq[256 + col];
    }

    // ---- phase 2: grid barrier (replay-safe monotonic ticket).
    // All 128 CTAs are co-resident (1 CTA/SM, 128 <= #SMs) -> no deadlock.
    __threadfence();
    __syncthreads();
    if (tid == 0) {
        const unsigned int ticket = atomicAdd(&g_bar, 1u);
        const unsigned int target = (ticket / GRID_CTAS + 1u) * GRID_CTAS;
        while (ld_acquire_gpu(&g_bar) < target) { }
    }
    __syncthreads();

    // ---- phase 3: per-column affine for this CTA's 256 columns
    float* smc = reinterpret_cast<float*>(sm);          // scale [256]
    float* smh = reinterpret_cast<float*>(sm) + 256;    // shift [256]
    {
        const int col = block_o + tid;
        float S = 0.0f, SS = 0.0f;
        #pragma unroll
        for (int i = 0; i < 32; i++) { S += g_psum[i][col]; SS += g_psqsum[i][col]; }
        const float inv_n = 1.0f / (float)BATCH;
        const float mean = S * inv_n;
        const float var  = SS * inv_n - mean * mean;
        const float rstd = rsqrtf(var + BN_EPS);
        const float sc = rstd * gamma[col];
        smc[tid] = sc;
        smh[tid] = fmaf(-mean, sc, beta[col]);
    }
    __syncthreads();

    // ---- phase 4: normalize accumulators and store Y once
    #pragma unroll
    for (int mt = 0; mt < 4; mt++) {
        #pragma unroll
        for (int nt = 0; nt < 8; nt++) {
            const int colT = warp_n * 64 + nt * 8 + 2 * tig;
            const float scx = smc[colT],     scy = smc[colT + 1];
            const float shx = smh[colT],     shy = smh[colT + 1];
            const int row = block_b + warp_m * 64 + mt * 16 + g;
            const int col = block_o + colT;
            float2 lo = make_float2(fmaf(acc[mt][nt][0], scx, shx),
                                    fmaf(acc[mt][nt][1], scy, shy));
            float2 hi = make_float2(fmaf(acc[mt][nt][2], scx, shx),
                                    fmaf(acc[mt][nt][3], scy, shy));
            *reinterpret_cast<float2*>(Y + (size_t)row * OUTF + col) = lo;
            *reinterpret_cast<float2*>(Y + (size_t)(row + 8) * OUTF + col) = hi;
        }
    }
}

// ---------------------------------------------------------------------------
// Launcher. Inputs: x, c1, c2, c3, bias(skipped: cancels under BN), gamma, beta
// ---------------------------------------------------------------------------
extern "C" void kernel_launch(void* const* d_in, const int* in_sizes, int n_in,
                              void* d_out, int out_size)
{
    (void)in_sizes; (void)n_in; (void)out_size;
    const float* x     = (const float*)d_in[0];
    const float* c1    = (const float*)d_in[1];
    const float* c2    = (const float*)d_in[2];
    const float* c3    = (const float*)d_in[3];
    const float* gamma = (const float*)d_in[5];
    const float* beta  = (const float*)d_in[6];
    float* y = (float*)d_out;

    cudaFuncSetAttribute(poly_mma_bn_kernel,
                         cudaFuncAttributeMaxDynamicSharedMemorySize, SMEM_BYTES);

    pack_kernel<<<4096 + 1024, 256>>>(x, c1, c2, c3);

    dim3 grid(OUTF / TILE_N, BATCH / TILE_M);   // (4, 32) = 128 CTAs
    poly_mma_bn_kernel<<<grid, 256, SMEM_BYTES>>>(y, gamma, beta);
}

// round 12
// speedup vs baseline: 7.8293x; 1.1976x over previous
#include <cuda_runtime.h>
#include <cuda_fp16.h>
#include <cstdint>
#include <math.h>

// Problem constants: B=4096, OUT=1024, IN=1024
#define BATCH 4096
#define OUTF  1024
#define INF   1024
#define KTOT  3072            // 3 * INF (x | x^2 | x^3 concatenated on K)
#define BN_EPS 1e-5f
#define GRID_CTAS 128

// ---------------------------------------------------------------------------
// Scratch (__device__ globals; no allocations allowed)
// ---------------------------------------------------------------------------
__device__ __half g_A[(size_t)BATCH * KTOT];   // 24 MB: [x | x^2 | x^3] fp16
__device__ __half g_B[(size_t)OUTF * KTOT];    //  6 MB: [c1 | c2 | c3] fp16
__device__ float g_psum[32][OUTF];
__device__ float g_psqsum[32][OUTF];
__device__ unsigned int g_bar = 0;             // monotonic grid-barrier ticket

// ---------------------------------------------------------------------------
// Baseline-PTX helpers (sm_80 features only: harness compiles via compute_103)
// ---------------------------------------------------------------------------
__device__ __forceinline__ uint32_t smem_u32(const void* p) {
    uint32_t a;
    asm("{ .reg .u64 t; cvta.to.shared.u64 t, %1; cvt.u32.u64 %0, t; }" : "=r"(a) : "l"(p));
    return a;
}
__device__ __forceinline__ void cp16(uint32_t dst, const void* src) {
    asm volatile("cp.async.cg.shared.global [%0], [%1], 16;" :: "r"(dst), "l"(src));
}
__device__ __forceinline__ uint32_t pack_h2(float lo, float hi) {
    __half2 h = __floats2half2_rn(lo, hi);
    return *reinterpret_cast<uint32_t*>(&h);
}
__device__ __forceinline__ unsigned int ld_acquire_gpu(const unsigned int* p) {
    unsigned int v;
    asm volatile("ld.acquire.gpu.u32 %0, [%1];" : "=r"(v) : "l"(p) : "memory");
    return v;
}

// m16n8k16 fp16 tensor-core MMA (sm_80 baseline PTX), fp32 accumulate
#define MMA_F16(d, a, b) \
    asm volatile("mma.sync.aligned.m16n8k16.row.col.f32.f16.f16.f32 " \
        "{%0,%1,%2,%3}, {%4,%5,%6,%7}, {%8,%9}, {%0,%1,%2,%3};" \
        : "+f"((d)[0]), "+f"((d)[1]), "+f"((d)[2]), "+f"((d)[3]) \
        : "r"((a)[0]), "r"((a)[1]), "r"((a)[2]), "r"((a)[3]), \
          "r"((b)[0]), "r"((b)[1]))

// ldmatrix m8n8.x4 (sm_75+ baseline PTX)
#define LDSM_X4(r0, r1, r2, r3, addr) \
    asm volatile("ldmatrix.sync.aligned.m8n8.x4.shared.b16 {%0,%1,%2,%3}, [%4];" \
        : "=r"(r0), "=r"(r1), "=r"(r2), "=r"(r3) : "r"(addr))

// ---------------------------------------------------------------------------
// Pre-pass: pack A = [x|x^2|x^3] and B = [c1|c2|c3] as fp16.
// Blocks [0,4096) -> A; [4096,5120) -> B.
// ---------------------------------------------------------------------------
__global__ __launch_bounds__(256)
void pack_kernel(const float* __restrict__ X,
                 const float* __restrict__ C1,
                 const float* __restrict__ C2,
                 const float* __restrict__ C3)
{
    if (blockIdx.x < 4096) {
        const int idx = blockIdx.x * 256 + threadIdx.x;
        const int b  = idx >> 8;
        const int k4 = (idx & 255) * 4;
        const float4 v = *reinterpret_cast<const float4*>(X + (size_t)b * INF + k4);
        float4 s, c;
        s.x = v.x * v.x; s.y = v.y * v.y; s.z = v.z * v.z; s.w = v.w * v.w;
        c.x = s.x * v.x; c.y = s.y * v.y; c.z = s.z * v.z; c.w = s.w * v.w;
        __half* rowp = g_A + (size_t)b * KTOT;
        uint2 h;
        h.x = pack_h2(v.x, v.y); h.y = pack_h2(v.z, v.w);
        *reinterpret_cast<uint2*>(rowp + k4) = h;
        h.x = pack_h2(s.x, s.y); h.y = pack_h2(s.z, s.w);
        *reinterpret_cast<uint2*>(rowp + INF + k4) = h;
        h.x = pack_h2(c.x, c.y); h.y = pack_h2(c.z, c.w);
        *reinterpret_cast<uint2*>(rowp + 2 * INF + k4) = h;
    } else {
        const int idx = (blockIdx.x - 4096) * 256 + threadIdx.x;
        const int o  = idx >> 8;
        const int k4 = (idx & 255) * 4;
        const size_t src = (size_t)o * INF + k4;
        __half* rowp = g_B + (size_t)o * KTOT;
        float4 v; uint2 h;
        v = *reinterpret_cast<const float4*>(C1 + src);
        h.x = pack_h2(v.x, v.y); h.y = pack_h2(v.z, v.w);
        *reinterpret_cast<uint2*>(rowp + k4) = h;
        v = *reinterpret_cast<const float4*>(C2 + src);
        h.x = pack_h2(v.x, v.y); h.y = pack_h2(v.z, v.w);
        *reinterpret_cast<uint2*>(rowp + INF + k4) = h;
        v = *reinterpret_cast<const float4*>(C3 + src);
        h.x = pack_h2(v.x, v.y); h.y = pack_h2(v.z, v.w);
        *reinterpret_cast<uint2*>(rowp + 2 * INF + k4) = h;
    }
}

// ---------------------------------------------------------------------------
// Fully fused: fp16 GEMM (M=4096,N=1024,K=3072) + BN stats + grid barrier +
// BN finalize + normalized store.
// CTA tile 128x256, 512 threads = 16 warps (2m x 8n), warp tile 64x32
// -> 4 warps/SMSP for latency hiding (the R10 limiter: tensor idle 60%).
// Grid = (4,32) = 128 CTAs at 1 CTA/SM -> co-resident; grid barrier safe.
// ---------------------------------------------------------------------------
#define TILE_M 128
#define TILE_N 256
#define KCH    32
#define NCHUNK (KTOT / KCH)        // 96
#define RBB    80                  // bytes per smem row (64 data + 16 pad)
#define MATB_A (128 * RBB)         // 10240 B
#define MATB_B (256 * RBB)         // 20480 B
#define STAGEB (MATB_A + MATB_B)   // 30720 B
#define SMEM_BYTES (4 * STAGEB)    // 122880 B

__global__ __launch_bounds__(512, 1)
void poly_mma_bn_kernel(float* __restrict__ Y,
                        const float* __restrict__ gamma,
                        const float* __restrict__ beta)
{
    extern __shared__ char sm[];
    const uint32_t smbase = smem_u32(sm);

    const int tid  = threadIdx.x;
    const int wid  = tid >> 5;
    const int lane = tid & 31;
    const int g    = lane >> 2;      // 0..7
    const int tig  = lane & 3;       // 0..3
    const int warp_m = wid >> 3;     // 0..1  -> m base = warp_m*64
    const int warp_n = wid & 7;      // 0..7  -> n base = warp_n*32

    const int block_o = blockIdx.x * TILE_N;
    const int block_b = blockIdx.y * TILE_M;

    // ldmatrix per-lane address components
    const int quad = lane >> 3;
    const int rq   = lane & 7;
    // A x4: (rows+0,k-lo)(rows+8,k-lo)(rows+0,k-hi)(rows+8,k-hi)
    const uint32_t a_lane_off = (uint32_t)((((quad & 1) * 8) + rq) * RBB + (quad >> 1) * 16);
    // B x4: (n+0,k-lo)(n+0,k-hi)(n+8,k-lo)(n+8,k-hi)
    const uint32_t b_lane_off = (uint32_t)((((quad >> 1) * 8) + rq) * RBB + (quad & 1) * 16);

    // cp.async geometry (512 threads, 3 cp16 each per chunk):
    //   A: 128 rows x 4 16B pieces = 512 -> 1 per thread
    //   B: 256 rows x 4 16B pieces = 1024 -> 2 per thread (rows r, r+128)
    const int crow = tid >> 2;          // 0..127
    const int qc   = tid & 3;           // 16B piece index
    const __half* srcA  = g_A + (size_t)(block_b + crow) * KTOT + qc * 8;
    const __half* srcB0 = g_B + (size_t)(block_o + crow) * KTOT + qc * 8;
    const __half* srcB1 = g_B + (size_t)(block_o + crow + 128) * KTOT + qc * 8;
    const uint32_t cdst = (uint32_t)(crow * RBB + qc * 16);

    float acc[4][4][4];
    #pragma unroll
    for (int mt = 0; mt < 4; mt++)
        #pragma unroll
        for (int nt = 0; nt < 4; nt++)
            #pragma unroll
            for (int r = 0; r < 4; r++)
                acc[mt][nt][r] = 0.0f;

    auto stage_chunk = [&](int s) {
        if (s < NCHUNK) {
            const uint32_t base = smbase + (uint32_t)((s & 3) * STAGEB);
            const int k0 = s * KCH;
            cp16(base + cdst, srcA + k0);
            const uint32_t bB = base + MATB_A;
            cp16(bB + cdst,             srcB0 + k0);
            cp16(bB + cdst + 128 * RBB, srcB1 + k0);
        }
        asm volatile("cp.async.commit_group;" ::: "memory");
    };

    stage_chunk(0);
    stage_chunk(1);
    stage_chunk(2);

    const uint32_t a_warp = (uint32_t)(warp_m * 64 * RBB) + a_lane_off;
    const uint32_t b_warp = (uint32_t)(warp_n * 32 * RBB) + b_lane_off;

    for (int s = 0; s < NCHUNK; ++s) {
        asm volatile("cp.async.wait_group 2;" ::: "memory");
        __syncthreads();

        stage_chunk(s + 3);

        const uint32_t stA = smbase + (uint32_t)((s & 3) * STAGEB);
        const uint32_t stB = stA + MATB_A;

        #pragma unroll
        for (int kk = 0; kk < 2; kk++) {
            const uint32_t kb = (uint32_t)(kk * 32);

            uint32_t a[4][4];
            #pragma unroll
            for (int mt = 0; mt < 4; mt++)
                LDSM_X4(a[mt][0], a[mt][1], a[mt][2], a[mt][3],
                        stA + a_warp + (uint32_t)(mt * 16 * RBB) + kb);

            uint32_t b[4][2];
            #pragma unroll
            for (int p = 0; p < 2; p++)
                LDSM_X4(b[2 * p][0], b[2 * p][1], b[2 * p + 1][0], b[2 * p + 1][1],
                        stB + b_warp + (uint32_t)(p * 16 * RBB) + kb);

            #pragma unroll
            for (int mt = 0; mt < 4; mt++)
                #pragma unroll
                for (int nt = 0; nt < 4; nt++)
                    MMA_F16(acc[mt][nt], a[mt], b[nt]);
        }
    }

    // ---- phase 1: BN partial stats for this 128-row block (registers only)
    float csum[4][2], csq[4][2];
    #pragma unroll
    for (int nt = 0; nt < 4; nt++)
        #pragma unroll
        for (int c = 0; c < 2; c++) {
            float s0 = 0.0f, q0 = 0.0f;
            #pragma unroll
            for (int mt = 0; mt < 4; mt++) {
                const float vlo = acc[mt][nt][c];
                const float vhi = acc[mt][nt][c + 2];
                s0 += vlo + vhi;
                q0 = fmaf(vlo, vlo, q0);
                q0 = fmaf(vhi, vhi, q0);
            }
            csum[nt][c] = s0;
            csq[nt][c] = q0;
        }
    #pragma unroll
    for (int d = 4; d <= 16; d <<= 1) {
        #pragma unroll
        for (int nt = 0; nt < 4; nt++)
            #pragma unroll
            for (int c = 0; c < 2; c++) {
                csum[nt][c] += __shfl_xor_sync(0xFFFFFFFFu, csum[nt][c], d);
                csq[nt][c]  += __shfl_xor_sync(0xFFFFFFFFu, csq[nt][c], d);
            }
    }
    float* red_sum = reinterpret_cast<float*>(sm);          // [2][256]
    float* red_sq  = reinterpret_cast<float*>(sm) + 512;    // [2][256]
    __syncthreads();
    if (g == 0) {
        #pragma unroll
        for (int nt = 0; nt < 4; nt++)
            #pragma unroll
            for (int c = 0; c < 2; c++) {
                const int col = warp_n * 32 + nt * 8 + 2 * tig + c;
                red_sum[warp_m * 256 + col] = csum[nt][c];
                red_sq [warp_m * 256 + col] = csq[nt][c];
            }
    }
    __syncthreads();
    if (tid < 256) {
        g_psum[blockIdx.y][block_o + tid]   = red_sum[tid] + red_sum[256 + tid];
        g_psqsum[blockIdx.y][block_o + tid] = red_sq[tid]  + red_sq[256 + tid];
    }

    // ---- phase 2: grid barrier (replay-safe monotonic ticket).
    // All 128 CTAs co-resident (1 CTA/SM, 128 <= #SMs) -> no deadlock.
    __threadfence();
    __syncthreads();
    if (tid == 0) {
        const unsigned int ticket = atomicAdd(&g_bar, 1u);
        const unsigned int target = (ticket / GRID_CTAS + 1u) * GRID_CTAS;
        while (ld_acquire_gpu(&g_bar) < target) { }
    }
    __syncthreads();

    // ---- phase 3: per-column affine for this CTA's 256 columns
    float* smc = reinterpret_cast<float*>(sm);          // scale [256]
    float* smh = reinterpret_cast<float*>(sm) + 256;    // shift [256]
    if (tid < 256) {
        const int col = block_o + tid;
        float S = 0.0f, SS = 0.0f;
        #pragma unroll
        for (int i = 0; i < 32; i++) { S += g_psum[i][col]; SS += g_psqsum[i][col]; }
        const float inv_n = 1.0f / (float)BATCH;
        const float mean = S * inv_n;
        const float var  = SS * inv_n - mean * mean;
        const float rstd = rsqrtf(var + BN_EPS);
        const float sc = rstd * gamma[col];
        smc[tid] = sc;
        smh[tid] = fmaf(-mean, sc, beta[col]);
    }
    __syncthreads();

    // ---- phase 4: normalize accumulators and store Y once
    #pragma unroll
    for (int mt = 0; mt < 4; mt++) {
        #pragma unroll
        for (int nt = 0; nt < 4; nt++) {
            const int colT = warp_n * 32 + nt * 8 + 2 * tig;
            const float scx = smc[colT],     scy = smc[colT + 1];
            const float shx = smh[colT],     shy = smh[colT + 1];
            const int row = block_b + warp_m * 64 + mt * 16 + g;
            const int col = block_o + colT;
            float2 lo = make_float2(fmaf(acc[mt][nt][0], scx, shx),
                                    fmaf(acc[mt][nt][1], scy, shy));
            float2 hi = make_float2(fmaf(acc[mt][nt][2], scx, shx),
                                    fmaf(acc[mt][nt][3], scy, shy));
            *reinterpret_cast<float2*>(Y + (size_t)row * OUTF + col) = lo;
            *reinterpret_cast<float2*>(Y + (size_t)(row + 8) * OUTF + col) = hi;
        }
    }
}

// ---------------------------------------------------------------------------
// Launcher. Inputs: x, c1, c2, c3, bias(skipped: cancels under BN), gamma, beta
// ---------------------------------------------------------------------------
extern "C" void kernel_launch(void* const* d_in, const int* in_sizes, int n_in,
                              void* d_out, int out_size)
{
    (void)in_sizes; (void)n_in; (void)out_size;
    const float* x     = (const float*)d_in[0];
    const float* c1    = (const float*)d_in[1];
    const float* c2    = (const float*)d_in[2];
    const float* c3    = (const float*)d_in[3];
    const float* gamma = (const float*)d_in[5];
    const float* beta  = (const float*)d_in[6];
    float* y = (float*)d_out;

    cudaFuncSetAttribute(poly_mma_bn_kernel,
                         cudaFuncAttributeMaxDynamicSharedMemorySize, SMEM_BYTES);

    pack_kernel<<<4096 + 1024, 256>>>(x, c1, c2, c3);

    dim3 grid(OUTF / TILE_N, BATCH / TILE_M);   // (4, 32) = 128 CTAs
    poly_mma_bn_kernel<<<grid, 512, SMEM_BYTES>>>(y, gamma, beta);
}